// round 3
// baseline (speedup 1.0000x reference)
#include <cuda_runtime.h>
#include <cstdint>

#define EPSF 1e-9f
typedef unsigned long long u64;

// ---------------- persistent device scratch (no allocs allowed) ----------------
__device__ float g_h1[256*256*400];        // conv1 out (B,256,20,20)   105MB
__device__ float g_wT[20736*256];          // caps1 weights [k][co]      21MB
__device__ float g_h2a[256*256*36];        // caps1 accum                9.4MB
__device__ float g_h2[256*256*36];         // caps1 relu'd               9.4MB
__device__ float g_u[256u*1152*10*16];     // prediction vectors        189MB
__device__ float g_blog[256*11520];        // routing logits            11.8MB
__device__ float g_masked[256*16];
__device__ float g_fc1[256*512];
__device__ float g_fc2[256*1024];

// ---------------- helpers: packed f32x2 FMA (Blackwell) ----------------
__device__ __forceinline__ void fma2(u64& acc, u64 a, u64 b) {
    asm("fma.rn.f32x2 %0, %1, %2, %0;" : "+l"(acc) : "l"(a), "l"(b));
}
__device__ __forceinline__ u64 pack2(float lo, float hi) {
    u64 r; unsigned il = __float_as_uint(lo), ih = __float_as_uint(hi);
    asm("mov.b64 %0, {%1, %2};" : "=l"(r) : "r"(il), "r"(ih));
    return r;
}
__device__ __forceinline__ u64 pack_dup(float v) {
    u64 r; unsigned iv = __float_as_uint(v);
    asm("mov.b64 %0, {%1, %1};" : "=l"(r) : "r"(iv));
    return r;
}
__device__ __forceinline__ void unpack2(u64 v, float& lo, float& hi) {
    asm("mov.b64 {%0, %1}, %2;" : "=f"(lo), "=f"(hi) : "l"(v));
}

// ---------------- weight transpose: (256co, 20736k) -> wT[k][co] ----------------
__global__ void transpose_w_kernel(const float* __restrict__ w) {
    __shared__ float t[32][33];
    int k0 = blockIdx.x * 32, c0 = blockIdx.y * 32;
    int x = threadIdx.x, yy = threadIdx.y;
    #pragma unroll
    for (int r = yy; r < 32; r += 8)
        t[r][x] = w[(size_t)(c0 + r) * 20736 + k0 + x];
    __syncthreads();
    #pragma unroll
    for (int r = yy; r < 32; r += 8)
        g_wT[(size_t)(k0 + r) * 256 + c0 + x] = t[x][r];
}

// ---------------- conv1: (B,1,28,28) -> relu -> (B,256,20,20) ----------------
__global__ __launch_bounds__(256)
void conv1_kernel(const float* __restrict__ x, const float* __restrict__ w,
                  const float* __restrict__ bias) {
    __shared__ float img[784];
    __shared__ float ws[2592];                 // layout [tap][32 co]
    int b = blockIdx.y, co0 = blockIdx.x * 32;
    int tid = threadIdx.x;
    for (int i = tid; i < 784; i += 256) img[i] = x[b * 784 + i];
    for (int i = tid; i < 2592; i += 256) {
        int t = i >> 5, c = i & 31;
        ws[i] = w[(co0 + c) * 81 + t];
    }
    u64 b2[16];
    #pragma unroll
    for (int c = 0; c < 16; c++) b2[c] = pack2(bias[co0 + 2*c], bias[co0 + 2*c + 1]);
    __syncthreads();

    for (int p = tid; p < 400; p += 256) {
        int oy = p / 20, ox = p % 20;
        u64 acc[16];
        #pragma unroll
        for (int c = 0; c < 16; c++) acc[c] = b2[c];
        #pragma unroll 1
        for (int dy = 0; dy < 9; dy++) {
            const float* row = img + (oy + dy) * 28 + ox;
            u64 rr[9];
            #pragma unroll
            for (int dx = 0; dx < 9; dx++) rr[dx] = pack_dup(row[dx]);
            #pragma unroll
            for (int dx = 0; dx < 9; dx++) {
                const u64* wp = (const u64*)(ws + (dy * 9 + dx) * 32);
                #pragma unroll
                for (int c = 0; c < 16; c++) fma2(acc[c], wp[c], rr[dx]);
            }
        }
        #pragma unroll
        for (int c = 0; c < 16; c++) {
            float lo, hi; unpack2(acc[c], lo, hi);
            g_h1[((size_t)b * 256 + co0 + 2*c    ) * 400 + p] = fmaxf(lo, 0.f);
            g_h1[((size_t)b * 256 + co0 + 2*c + 1) * 400 + p] = fmaxf(hi, 0.f);
        }
    }
}

// ---------------- caps1 init / relu ----------------
__global__ void init_h2_kernel(const float* __restrict__ bias) {
    int idx = blockIdx.x * 256 + threadIdx.x;
    if (idx < 256*256*36) g_h2a[idx] = bias[(idx / 36) & 255];
}
__global__ void relu_h2_kernel() {
    int idx = blockIdx.x * 256 + threadIdx.x;
    if (idx < 256*256*36) g_h2[idx] = fmaxf(g_h2a[idx], 0.f);
}

// ---------------- caps1 conv: 256ch 9x9 s2 -> (B,256,6,6), partial over ci ----------------
// grid (4 ci-chunks, 256 batch), block 128 threads = 128 co-pairs.
__global__ __launch_bounds__(128, 3)
void caps1_kernel() {
    __shared__ float ch[400];
    int b = blockIdx.y, c0 = blockIdx.x * 64;
    int tid = threadIdx.x;
    u64 acc[36];
    #pragma unroll
    for (int p = 0; p < 36; p++) acc[p] = 0ULL;
    const float* h1b = g_h1 + (size_t)b * 102400;

    for (int ci = c0; ci < c0 + 64; ci++) {
        __syncthreads();
        #pragma unroll
        for (int idx = tid; idx < 400; idx += 128) ch[idx] = h1b[(size_t)ci * 400 + idx];
        __syncthreads();
        const float* wbase = g_wT + (size_t)ci * 81 * 256 + 2 * tid;
        #pragma unroll 1
        for (int dy = 0; dy < 9; dy++) {
            u64 w2[9];
            #pragma unroll
            for (int dx = 0; dx < 9; dx++)
                w2[dx] = *(const u64*)(wbase + (dy * 9 + dx) * 256);
            #pragma unroll
            for (int oy = 0; oy < 6; oy++) {
                const float* rowp = ch + (2 * oy + dy) * 20;
                u64 rr[19];
                #pragma unroll
                for (int c = 0; c < 19; c++) rr[c] = pack_dup(rowp[c]);
                #pragma unroll
                for (int dx = 0; dx < 9; dx++)
                    #pragma unroll
                    for (int ox = 0; ox < 6; ox++)
                        fma2(acc[oy * 6 + ox], w2[dx], rr[ox * 2 + dx]);
            }
        }
    }
    float* out0 = g_h2a + ((size_t)b * 256 + 2 * tid) * 36;
    #pragma unroll
    for (int p = 0; p < 36; p++) {
        float lo, hi; unpack2(acc[p], lo, hi);
        atomicAdd(out0 + p, lo);
        atomicAdd(out0 + 36 + p, hi);
    }
}

// ---------------- u = Wj @ x_tile  ->  g_u[b][i][j][m] ----------------
__global__ void u_kernel(const float* __restrict__ W) {
    int gid = blockIdx.x * 256 + threadIdx.x;
    if (gid >= 256 * 11520) return;
    int b = gid / 11520;
    int r = gid - b * 11520;               // r = i*10 + j
    const float* wb = W + (size_t)r * 128; // flat 16x8 view of (8,16)
    int base = r * 8;                      // i*80 + j*8
    const float* h2b = g_h2 + (size_t)b * 9216;
    float x8[8];
    #pragma unroll
    for (int n = 0; n < 8; n++) {
        int q = base + n;
        x8[n] = h2b[(q / 360) * 36 + (q % 36)];
    }
    float* up = g_u + (size_t)gid * 16;
    #pragma unroll
    for (int mm = 0; mm < 16; mm++) {
        const float* wr = wb + mm * 8;
        float s = 0.f;
        #pragma unroll
        for (int n = 0; n < 8; n++) s += wr[n] * x8[n];
        up[mm] = s;
    }
}

// ---------------- dynamic routing (3 iters), one block per batch ----------------
// 288 threads: (g = t/16 in [0,18), m = t%16). logits in g_blog (global scratch);
// static smem only (~13KB) so the launch config stays under the 48KB default.
__global__ __launch_bounds__(288)
void routing_kernel(const float* __restrict__ y, const float* __restrict__ bias_r,
                    float* __restrict__ out) {
    __shared__ float spart[18 * 160];
    __shared__ float sfull[160];
    __shared__ __align__(16) float sv[160];
    __shared__ float sscale[16];
    int b = blockIdx.x, t = threadIdx.x;
    const float* ub = g_u + (size_t)b * 184320;
    float* sb = g_blog + (size_t)b * 11520;
    int g = t >> 4, m = t & 15;

    for (int iter = 0; iter < 3; ++iter) {
        float acc[10];
        #pragma unroll
        for (int j = 0; j < 10; j++) acc[j] = 0.f;
        int i0 = g * 64;
        for (int i = i0; i < i0 + 64; i++) {
            float c[10];
            if (iter == 0) {
                #pragma unroll
                for (int j = 0; j < 10; j++) c[j] = 0.1f;
            } else {
                float mx = -1e30f;
                #pragma unroll
                for (int j = 0; j < 10; j++) { c[j] = sb[i * 10 + j]; mx = fmaxf(mx, c[j]); }
                float s = 0.f;
                #pragma unroll
                for (int j = 0; j < 10; j++) { c[j] = __expf(c[j] - mx); s += c[j]; }
                float inv = 1.f / s;
                #pragma unroll
                for (int j = 0; j < 10; j++) c[j] *= inv;
            }
            const float* up = ub + (size_t)i * 160 + m;
            #pragma unroll
            for (int j = 0; j < 10; j++) acc[j] += c[j] * up[j * 16];
        }
        #pragma unroll
        for (int j = 0; j < 10; j++) spart[g * 160 + j * 16 + m] = acc[j];
        __syncthreads();

        if (t < 160) {
            float s = bias_r[t];
            #pragma unroll
            for (int g2 = 0; g2 < 18; g2++) s += spart[g2 * 160 + t];
            sfull[t] = s;
        }
        __syncthreads();
        if (t < 10) {
            float n2 = 0.f;
            #pragma unroll
            for (int mm = 0; mm < 16; mm++) { float v = sfull[t * 16 + mm]; n2 += v * v; }
            sscale[t] = (n2 / (1.f + n2)) / sqrtf(n2 + EPSF);
        }
        __syncthreads();
        if (t < 160) sv[t] = sfull[t] * sscale[t >> 4];
        __syncthreads();

        if (iter < 2) {                                   // agreement update
            for (int idx = t; idx < 11520; idx += 288) {
                int j = idx % 10;
                const float4* up4 = (const float4*)(ub + (size_t)idx * 16);
                const float4* vv4 = (const float4*)(sv + j * 16);
                float d = 0.f;
                #pragma unroll
                for (int q = 0; q < 4; q++) {
                    float4 a = up4[q], v4 = vv4[q];
                    d += a.x * v4.x + a.y * v4.y + a.z * v4.z + a.w * v4.w;
                }
                if (iter == 0) sb[idx] = d; else sb[idx] += d;
            }
        }
        __syncthreads();
    }
    if (t < 10) {                                          // v_length
        float n2 = 0.f;
        #pragma unroll
        for (int mm = 0; mm < 16; mm++) { float v = sv[t * 16 + mm]; n2 += v * v; }
        out[b * 10 + t] = sqrtf(n2 + EPSF);
    }
    if (t < 16) {                                          // masked readout (flat (16,10) view)
        float s = 0.f;
        const float* yb = y + b * 10;
        #pragma unroll
        for (int tt = 0; tt < 10; tt++) s += sv[t * 10 + tt] * yb[tt];
        g_masked[b * 16 + t] = s;
    }
}

// ---------------- FC GEMM: C = act(A[M,K] @ Wt[N,K]^T + bias) ----------------
// which: 0 = masked->fc1 (K=16,N=512), 1 = fc1->fc2 (K=512,N=1024),
//        2 = fc2->out+2560 sigmoid (K=1024,N=784). A/C resolved in device code.
__global__ void gemm_kernel(const float* __restrict__ Wt, const float* __restrict__ bias,
                            float* __restrict__ out, int N, int K, int which) {
    __shared__ float As[16][16];
    __shared__ float Bs[16][17];
    const float* A; float* C;
    if (which == 0)      { A = g_masked; C = g_fc1; }
    else if (which == 1) { A = g_fc1;    C = g_fc2; }
    else                 { A = g_fc2;    C = out + 2560; }
    int tx = threadIdx.x, ty = threadIdx.y;
    int n0 = blockIdx.x * 16, m0 = blockIdx.y * 16;
    float acc = 0.f;
    for (int k0 = 0; k0 < K; k0 += 16) {
        As[ty][tx] = A[(size_t)(m0 + ty) * K + k0 + tx];
        Bs[ty][tx] = Wt[(size_t)(n0 + ty) * K + k0 + tx];
        __syncthreads();
        #pragma unroll
        for (int kk = 0; kk < 16; kk++) acc += As[ty][kk] * Bs[tx][kk];
        __syncthreads();
    }
    acc += bias[n0 + tx];
    if (which == 2) acc = 1.f / (1.f + expf(-acc));
    C[(size_t)(m0 + ty) * N + n0 + tx] = acc;
}

// ---------------- launch ----------------
extern "C" void kernel_launch(void* const* d_in, const int* in_sizes, int n_in,
                              void* d_out, int out_size) {
    (void)in_sizes; (void)n_in; (void)out_size;
    const float* x   = (const float*)d_in[0];
    const float* y   = (const float*)d_in[1];
    const float* c1w = (const float*)d_in[2];
    const float* c1b = (const float*)d_in[3];
    const float* c2w = (const float*)d_in[4];
    const float* c2b = (const float*)d_in[5];
    const float* W   = (const float*)d_in[6];
    const float* br  = (const float*)d_in[7];
    const float* f1w = (const float*)d_in[8];
    const float* f1b = (const float*)d_in[9];
    const float* f2w = (const float*)d_in[10];
    const float* f2b = (const float*)d_in[11];
    const float* f3w = (const float*)d_in[12];
    const float* f3b = (const float*)d_in[13];
    float* out = (float*)d_out;

    transpose_w_kernel<<<dim3(648, 8), dim3(32, 8)>>>(c2w);
    conv1_kernel<<<dim3(8, 256), 256>>>(x, c1w, c1b);
    init_h2_kernel<<<9216, 256>>>(c2b);
    caps1_kernel<<<dim3(4, 256), 128>>>();
    relu_h2_kernel<<<9216, 256>>>();
    u_kernel<<<11520, 256>>>(W);
    routing_kernel<<<256, 288>>>(y, br, out);
    gemm_kernel<<<dim3(32, 16), dim3(16, 16)>>>(f1w, f1b, out, 512, 16, 0);
    gemm_kernel<<<dim3(64, 16), dim3(16, 16)>>>(f2w, f2b, out, 1024, 512, 1);
    gemm_kernel<<<dim3(49, 16), dim3(16, 16)>>>(f3w, f3b, out, 784, 1024, 2);
}

// round 6
// speedup vs baseline: 1.1740x; 1.1740x over previous
#include <cuda_runtime.h>
#include <cuda_bf16.h>
#include <cstdint>

#define EPSF 1e-9f
typedef unsigned long long u64;
typedef unsigned int u32;

// ---------------- persistent device scratch ----------------
__device__ __nv_bfloat16 g_h1h[256*400*256];   // conv1 out NHWC, bf16 hi  52MB
__device__ __nv_bfloat16 g_h1l[256*400*256];   // conv1 out NHWC, bf16 lo  52MB
__device__ __nv_bfloat16 g_wbh[256*20736];     // caps1 W [co][tap*256+ci] hi
__device__ __nv_bfloat16 g_wbl[256*20736];     // caps1 W lo
__device__ float g_h2[256*256*36];             // caps1 out (relu'd)  [b][co][36]
__device__ float g_u[256u*1152*10*16];         // prediction vectors  189MB
__device__ float g_blog[256*11520];            // routing logits
__device__ float g_masked[256*16];
__device__ float g_fc1[256*512];
__device__ float g_fc2[256*1024];

// ---------------- helpers ----------------
__device__ __forceinline__ void fma2(u64& acc, u64 a, u64 b) {
    asm("fma.rn.f32x2 %0, %1, %2, %0;" : "+l"(acc) : "l"(a), "l"(b));
}
__device__ __forceinline__ u64 pack2(float lo, float hi) {
    u64 r; unsigned il = __float_as_uint(lo), ih = __float_as_uint(hi);
    asm("mov.b64 %0, {%1, %2};" : "=l"(r) : "r"(il), "r"(ih));
    return r;
}
__device__ __forceinline__ u64 pack_dup(float v) {
    u64 r; unsigned iv = __float_as_uint(v);
    asm("mov.b64 %0, {%1, %1};" : "=l"(r) : "r"(iv));
    return r;
}
__device__ __forceinline__ void unpack2(u64 v, float& lo, float& hi) {
    asm("mov.b64 {%0, %1}, %2;" : "=f"(lo), "=f"(hi) : "l"(v));
}
__device__ __forceinline__ u32 smem_u32(const void* p) {
    u32 a;
    asm("{ .reg .u64 t; cvta.to.shared.u64 t, %1; cvt.u32.u64 %0, t; }" : "=r"(a) : "l"(p));
    return a;
}
__device__ __forceinline__ void cp16(u32 dst, const void* src) {
    asm volatile("cp.async.cg.shared.global [%0], [%1], 16;" :: "r"(dst), "l"(src) : "memory");
}
__device__ __forceinline__ void cp_commit() { asm volatile("cp.async.commit_group;" ::: "memory"); }
#define CP_WAIT(n) asm volatile("cp.async.wait_group %0;" :: "n"(n) : "memory")

// bf16 warp MMA m16n8k16, fp32 accum (sm_80+; tensor pipe on sm_100)
#define MMA16816(c, a, b0, b1) \
    asm volatile("mma.sync.aligned.m16n8k16.row.col.f32.bf16.bf16.f32 " \
        "{%0,%1,%2,%3}, {%4,%5,%6,%7}, {%8,%9}, {%0,%1,%2,%3};" \
        : "+f"((c)[0]), "+f"((c)[1]), "+f"((c)[2]), "+f"((c)[3]) \
        : "r"((a)[0]), "r"((a)[1]), "r"((a)[2]), "r"((a)[3]), "r"(b0), "r"(b1))

// ---------------- weight prep: w[co][ci][9][9] fp32 -> wb[co][tap*256+ci] bf16 hi/lo ----------------
__global__ void prep_w_kernel(const float* __restrict__ w) {
    int k  = blockIdx.x * 256 + threadIdx.x;   // 0..20735 (grid.x = 81)
    int co = blockIdx.y;
    int tap = k >> 8, ci = k & 255;
    float v = w[(size_t)co * 20736 + ci * 81 + tap];
    __nv_bfloat16 h = __float2bfloat16(v);
    size_t dst = (size_t)co * 20736 + k;
    g_wbh[dst] = h;
    g_wbl[dst] = __float2bfloat16(v - __bfloat162float(h));
}

// ---------------- conv1: (B,1,28,28) -> relu -> NHWC bf16 hi/lo (B,20,20,256) ----------------
__global__ __launch_bounds__(256)
void conv1_kernel(const float* __restrict__ x, const float* __restrict__ w,
                  const float* __restrict__ bias) {
    __shared__ float img[784];
    __shared__ float ws[2592];                 // layout [tap][32 co]
    int b = blockIdx.y, co0 = blockIdx.x * 32;
    int tid = threadIdx.x;
    for (int i = tid; i < 784; i += 256) img[i] = x[b * 784 + i];
    for (int i = tid; i < 2592; i += 256) {
        int t = i >> 5, c = i & 31;
        ws[i] = w[(co0 + c) * 81 + t];
    }
    u64 b2[16];
    #pragma unroll
    for (int c = 0; c < 16; c++) b2[c] = pack2(bias[co0 + 2*c], bias[co0 + 2*c + 1]);
    __syncthreads();

    for (int p = tid; p < 400; p += 256) {
        int oy = p / 20, ox = p % 20;
        u64 acc[16];
        #pragma unroll
        for (int c = 0; c < 16; c++) acc[c] = b2[c];
        #pragma unroll 1
        for (int dy = 0; dy < 9; dy++) {
            const float* row = img + (oy + dy) * 28 + ox;
            u64 rr[9];
            #pragma unroll
            for (int dx = 0; dx < 9; dx++) rr[dx] = pack_dup(row[dx]);
            #pragma unroll
            for (int dx = 0; dx < 9; dx++) {
                const u64* wp = (const u64*)(ws + (dy * 9 + dx) * 32);
                #pragma unroll
                for (int c = 0; c < 16; c++) fma2(acc[c], wp[c], rr[dx]);
            }
        }
        size_t base = ((size_t)b * 400 + p) * 256 + co0;
        #pragma unroll
        for (int c = 0; c < 16; c++) {
            float lo, hi; unpack2(acc[c], lo, hi);
            lo = fmaxf(lo, 0.f); hi = fmaxf(hi, 0.f);
            __nv_bfloat16 hl = __float2bfloat16(lo);
            __nv_bfloat16 hh = __float2bfloat16(hi);
            float rl = lo - __bfloat162float(hl);
            float rh = hi - __bfloat162float(hh);
            *reinterpret_cast<__nv_bfloat162*>(&g_h1h[base + 2*c]) = __halves2bfloat162(hl, hh);
            *reinterpret_cast<__nv_bfloat162*>(&g_h1l[base + 2*c]) =
                __halves2bfloat162(__float2bfloat16(rl), __float2bfloat16(rh));
        }
    }
}

// ---------------- caps1 via mma.sync: C[9216,256] = A[9216,20736] @ W^T ----------------
// grid (2 n-tiles, 72 m-tiles), 256 thr = 8 warps (4x2), CTA tile 128x128,
// K-step 16 (one tap x 16 ci), 1296 steps, bf16 hi/lo 3-MMA split, 2-stage cp.async.
// smem stage: Ah 6K | Al 6K | Bh 6K | Bl 6K (rows padded to 48B), 2 stages = 48KB.
static constexpr int CSTG = 24576;
static constexpr u32 SMEM_C1 = 2 * CSTG;   // 49152 = default limit, no attribute needed

__global__ __launch_bounds__(256, 1)
void caps1_mma_kernel(const float* __restrict__ bias) {
    extern __shared__ char smem[];
    u32 sm = smem_u32(smem);
    int tid = threadIdx.x;
    int n0 = blockIdx.x * 128, m0 = blockIdx.y * 128;

    // loader addressing: thread -> (row rw, 16B chunk ch). cp16 moves 16B = 8 bf16,
    // so chunk ch covers elements [ch*8, ch*8+8) and smem bytes [ch*16, ch*16+16).
    int rw = tid >> 1, ch = tid & 1;
    int pl = m0 + rw;
    int pb = pl / 36, prr = pl % 36, loy = prr / 6, lox = prr % 6;
    u32 aPix = (u32)((pb * 20 + 2 * loy) * 20 + 2 * lox) * 256 + ch * 8;
    u32 bRow = (u32)(n0 + rw) * 20736 + ch * 8;
    u32 smOff = (u32)(rw * 48 + ch * 16);

    auto load_stage = [&](int s, int step) {
        u32 base = sm + s * CSTG;
        int tap = step >> 4, ci0 = (step & 15) * 16;
        int dy = tap / 9, dx = tap - dy * 9;
        u32 asrc = aPix + (u32)(dy * 20 + dx) * 256 + ci0;
        u32 bsrc = bRow + (u32)tap * 256 + ci0;
        cp16(base + smOff,         g_h1h + asrc);
        cp16(base + 6144 + smOff,  g_h1l + asrc);
        cp16(base + 12288 + smOff, g_wbh + bsrc);
        cp16(base + 18432 + smOff, g_wbl + bsrc);
        cp_commit();
    };

    int wid = tid >> 5, lane = tid & 31;
    int wm = wid & 3, wn = wid >> 2;               // warp tile: M 32, N 64
    int g = lane >> 2, tc = lane & 3;

    float c[2][8][4];
    #pragma unroll
    for (int i = 0; i < 2; i++)
        #pragma unroll
        for (int j = 0; j < 8; j++)
            #pragma unroll
            for (int q = 0; q < 4; q++) c[i][j][q] = 0.f;

    load_stage(0, 0);

    #pragma unroll 1
    for (int step = 0; step < 1296; step++) {
        int cur = step & 1;
        if (step + 1 < 1296) { load_stage(cur ^ 1, step + 1); CP_WAIT(1); }
        else CP_WAIT(0);
        __syncthreads();

        const u32* Ah = (const u32*)(smem + cur * CSTG);
        const u32* Al = Ah + 1536;
        const u32* Bh = Ah + 3072;
        const u32* Bl = Ah + 4608;
        // pitch = 12 words (48B). a0=A[r][tc*2..+1], a1=A[r+8][..], a2/a3 = k+8
        u32 ah[2][4], al[2][4];
        #pragma unroll
        for (int tm = 0; tm < 2; tm++) {
            int r = wm * 32 + tm * 16 + g;
            ah[tm][0] = Ah[r * 12 + tc];       ah[tm][1] = Ah[(r + 8) * 12 + tc];
            ah[tm][2] = Ah[r * 12 + tc + 4];   ah[tm][3] = Ah[(r + 8) * 12 + tc + 4];
            al[tm][0] = Al[r * 12 + tc];       al[tm][1] = Al[(r + 8) * 12 + tc];
            al[tm][2] = Al[r * 12 + tc + 4];   al[tm][3] = Al[(r + 8) * 12 + tc + 4];
        }
        #pragma unroll
        for (int tn = 0; tn < 8; tn++) {
            int n = wn * 64 + tn * 8 + g;
            u32 bh0 = Bh[n * 12 + tc], bh1 = Bh[n * 12 + tc + 4];
            u32 bl0 = Bl[n * 12 + tc], bl1 = Bl[n * 12 + tc + 4];
            #pragma unroll
            for (int tm = 0; tm < 2; tm++) {
                MMA16816(c[tm][tn], ah[tm], bh0, bh1);
                MMA16816(c[tm][tn], ah[tm], bl0, bl1);
                MMA16816(c[tm][tn], al[tm], bh0, bh1);
            }
        }
        __syncthreads();
    }

    // epilogue: bias + relu -> g_h2[b][co][36]
    #pragma unroll
    for (int tm = 0; tm < 2; tm++) {
        int r0 = m0 + wm * 32 + tm * 16 + g;
        int b0i = r0 / 36, rr0 = r0 % 36;
        int r1 = r0 + 8;
        int b1i = r1 / 36, rr1 = r1 % 36;
        float* d0 = g_h2 + (size_t)b0i * 9216 + rr0;
        float* d1 = g_h2 + (size_t)b1i * 9216 + rr1;
        #pragma unroll
        for (int tn = 0; tn < 8; tn++) {
            int cc = n0 + wn * 64 + tn * 8 + tc * 2;
            float bv0 = bias[cc], bv1 = bias[cc + 1];
            d0[(size_t)cc * 36]       = fmaxf(c[tm][tn][0] + bv0, 0.f);
            d0[(size_t)(cc + 1) * 36] = fmaxf(c[tm][tn][1] + bv1, 0.f);
            d1[(size_t)cc * 36]       = fmaxf(c[tm][tn][2] + bv0, 0.f);
            d1[(size_t)(cc + 1) * 36] = fmaxf(c[tm][tn][3] + bv1, 0.f);
        }
    }
}

// ---------------- u = Wj @ x_tile  ->  g_u[b][i][j][m] ----------------
__global__ void u_kernel(const float* __restrict__ W) {
    int gid = blockIdx.x * 256 + threadIdx.x;
    if (gid >= 256 * 11520) return;
    int b = gid / 11520;
    int r = gid - b * 11520;               // r = i*10 + j
    const float* wb = W + (size_t)r * 128; // flat 16x8 view of (8,16)
    int base = r * 8;                      // i*80 + j*8
    const float* h2b = g_h2 + (size_t)b * 9216;
    float x8[8];
    #pragma unroll
    for (int n = 0; n < 8; n++) {
        int q = base + n;
        x8[n] = h2b[(q / 360) * 36 + (q % 36)];
    }
    float* up = g_u + (size_t)gid * 16;
    #pragma unroll
    for (int mm = 0; mm < 16; mm++) {
        const float* wr = wb + mm * 8;
        float s = 0.f;
        #pragma unroll
        for (int n = 0; n < 8; n++) s += wr[n] * x8[n];
        up[mm] = s;
    }
}

// ---------------- dynamic routing (3 iters), one block per batch ----------------
__global__ __launch_bounds__(288)
void routing_kernel(const float* __restrict__ y, const float* __restrict__ bias_r,
                    float* __restrict__ out) {
    __shared__ float spart[18 * 160];
    __shared__ float sfull[160];
    __shared__ __align__(16) float sv[160];
    __shared__ float sscale[16];
    int b = blockIdx.x, t = threadIdx.x;
    const float* ub = g_u + (size_t)b * 184320;
    float* sb = g_blog + (size_t)b * 11520;
    int g = t >> 4, m = t & 15;

    for (int iter = 0; iter < 3; ++iter) {
        float acc[10];
        #pragma unroll
        for (int j = 0; j < 10; j++) acc[j] = 0.f;
        int i0 = g * 64;
        for (int i = i0; i < i0 + 64; i++) {
            float c[10];
            if (iter == 0) {
                #pragma unroll
                for (int j = 0; j < 10; j++) c[j] = 0.1f;
            } else {
                float mx = -1e30f;
                #pragma unroll
                for (int j = 0; j < 10; j++) { c[j] = sb[i * 10 + j]; mx = fmaxf(mx, c[j]); }
                float s = 0.f;
                #pragma unroll
                for (int j = 0; j < 10; j++) { c[j] = __expf(c[j] - mx); s += c[j]; }
                float inv = 1.f / s;
                #pragma unroll
                for (int j = 0; j < 10; j++) c[j] *= inv;
            }
            const float* up = ub + (size_t)i * 160 + m;
            #pragma unroll
            for (int j = 0; j < 10; j++) acc[j] += c[j] * up[j * 16];
        }
        #pragma unroll
        for (int j = 0; j < 10; j++) spart[g * 160 + j * 16 + m] = acc[j];
        __syncthreads();

        if (t < 160) {
            float s = bias_r[t];
            #pragma unroll
            for (int g2 = 0; g2 < 18; g2++) s += spart[g2 * 160 + t];
            sfull[t] = s;
        }
        __syncthreads();
        if (t < 10) {
            float n2 = 0.f;
            #pragma unroll
            for (int mm = 0; mm < 16; mm++) { float v = sfull[t * 16 + mm]; n2 += v * v; }
            sscale[t] = (n2 / (1.f + n2)) / sqrtf(n2 + EPSF);
        }
        __syncthreads();
        if (t < 160) sv[t] = sfull[t] * sscale[t >> 4];
        __syncthreads();

        if (iter < 2) {
            for (int idx = t; idx < 11520; idx += 288) {
                int j = idx % 10;
                const float4* up4 = (const float4*)(ub + (size_t)idx * 16);
                const float4* vv4 = (const float4*)(sv + j * 16);
                float d = 0.f;
                #pragma unroll
                for (int q = 0; q < 4; q++) {
                    float4 a = up4[q], v4 = vv4[q];
                    d += a.x * v4.x + a.y * v4.y + a.z * v4.z + a.w * v4.w;
                }
                if (iter == 0) sb[idx] = d; else sb[idx] += d;
            }
        }
        __syncthreads();
    }
    if (t < 10) {
        float n2 = 0.f;
        #pragma unroll
        for (int mm = 0; mm < 16; mm++) { float v = sv[t * 16 + mm]; n2 += v * v; }
        out[b * 10 + t] = sqrtf(n2 + EPSF);
    }
    if (t < 16) {
        float s = 0.f;
        const float* yb = y + b * 10;
        #pragma unroll
        for (int tt = 0; tt < 10; tt++) s += sv[t * 10 + tt] * yb[tt];
        g_masked[b * 16 + t] = s;
    }
}

// ---------------- FC GEMM ----------------
__global__ void gemm_kernel(const float* __restrict__ Wt, const float* __restrict__ bias,
                            float* __restrict__ out, int N, int K, int which) {
    __shared__ float As[16][16];
    __shared__ float Bs[16][17];
    const float* A; float* C;
    if (which == 0)      { A = g_masked; C = g_fc1; }
    else if (which == 1) { A = g_fc1;    C = g_fc2; }
    else                 { A = g_fc2;    C = out + 2560; }
    int tx = threadIdx.x, ty = threadIdx.y;
    int n0 = blockIdx.x * 16, m0 = blockIdx.y * 16;
    float acc = 0.f;
    for (int k0 = 0; k0 < K; k0 += 16) {
        As[ty][tx] = A[(size_t)(m0 + ty) * K + k0 + tx];
        Bs[ty][tx] = Wt[(size_t)(n0 + ty) * K + k0 + tx];
        __syncthreads();
        #pragma unroll
        for (int kk = 0; kk < 16; kk++) acc += As[ty][kk] * Bs[tx][kk];
        __syncthreads();
    }
    acc += bias[n0 + tx];
    if (which == 2) acc = 1.f / (1.f + expf(-acc));
    C[(size_t)(m0 + ty) * N + n0 + tx] = acc;
}

// ---------------- launch ----------------
extern "C" void kernel_launch(void* const* d_in, const int* in_sizes, int n_in,
                              void* d_out, int out_size) {
    (void)in_sizes; (void)n_in; (void)out_size;
    const float* x   = (const float*)d_in[0];
    const float* y   = (const float*)d_in[1];
    const float* c1w = (const float*)d_in[2];
    const float* c1b = (const float*)d_in[3];
    const float* c2w = (const float*)d_in[4];
    const float* c2b = (const float*)d_in[5];
    const float* W   = (const float*)d_in[6];
    const float* br  = (const float*)d_in[7];
    const float* f1w = (const float*)d_in[8];
    const float* f1b = (const float*)d_in[9];
    const float* f2w = (const float*)d_in[10];
    const float* f2b = (const float*)d_in[11];
    const float* f3w = (const float*)d_in[12];
    const float* f3b = (const float*)d_in[13];
    float* out = (float*)d_out;

    prep_w_kernel<<<dim3(81, 256), 256>>>(c2w);
    conv1_kernel<<<dim3(8, 256), 256>>>(x, c1w, c1b);
    caps1_mma_kernel<<<dim3(2, 72), 256, SMEM_C1>>>(c2b);
    u_kernel<<<11520, 256>>>(W);
    routing_kernel<<<256, 288>>>(y, br, out);
    gemm_kernel<<<dim3(32, 16), dim3(16, 16)>>>(f1w, f1b, out, 512, 16, 0);
    gemm_kernel<<<dim3(64, 16), dim3(16, 16)>>>(f2w, f2b, out, 1024, 512, 1);
    gemm_kernel<<<dim3(49, 16), dim3(16, 16)>>>(f3w, f3b, out, 784, 1024, 2);
}

// round 7
// speedup vs baseline: 1.7988x; 1.5321x over previous
#include <cuda_runtime.h>
#include <cuda_bf16.h>
#include <cstdint>

#define EPSF 1e-9f
typedef unsigned long long u64;
typedef unsigned int u32;

// ---------------- persistent device scratch ----------------
__device__ __nv_bfloat16 g_h1h[256*400*256];   // conv1 out NHWC, bf16 hi  52MB
__device__ __nv_bfloat16 g_h1l[256*400*256];   // conv1 out NHWC, bf16 lo  52MB
__device__ __nv_bfloat16 g_wbh[256*20736];     // caps1 W [co][tap*256+ci] hi
__device__ __nv_bfloat16 g_wbl[256*20736];     // caps1 W lo
__device__ float g_h2[256*256*36];             // caps1 out (relu'd)  [b][co][36]
__device__ float g_u[256u*1152*10*16];         // prediction vectors  189MB
__device__ float g_blog[256*11520];            // routing logits
__device__ float g_masked[256*16];
__device__ float g_fc1[256*512];
__device__ float g_fc2[256*1024];

// ---------------- helpers ----------------
__device__ __forceinline__ void fma2(u64& acc, u64 a, u64 b) {
    asm("fma.rn.f32x2 %0, %1, %2, %0;" : "+l"(acc) : "l"(a), "l"(b));
}
__device__ __forceinline__ u64 pack2(float lo, float hi) {
    u64 r; unsigned il = __float_as_uint(lo), ih = __float_as_uint(hi);
    asm("mov.b64 %0, {%1, %2};" : "=l"(r) : "r"(il), "r"(ih));
    return r;
}
__device__ __forceinline__ u64 pack_dup(float v) {
    u64 r; unsigned iv = __float_as_uint(v);
    asm("mov.b64 %0, {%1, %1};" : "=l"(r) : "r"(iv));
    return r;
}
__device__ __forceinline__ void unpack2(u64 v, float& lo, float& hi) {
    asm("mov.b64 {%0, %1}, %2;" : "=f"(lo), "=f"(hi) : "l"(v));
}
__device__ __forceinline__ u32 smem_u32(const void* p) {
    u32 a;
    asm("{ .reg .u64 t; cvta.to.shared.u64 t, %1; cvt.u32.u64 %0, t; }" : "=r"(a) : "l"(p));
    return a;
}
__device__ __forceinline__ void cp16(u32 dst, const void* src) {
    asm volatile("cp.async.cg.shared.global [%0], [%1], 16;" :: "r"(dst), "l"(src) : "memory");
}
__device__ __forceinline__ void cp_commit() { asm volatile("cp.async.commit_group;" ::: "memory"); }
#define CP_WAIT(n) asm volatile("cp.async.wait_group %0;" :: "n"(n) : "memory")

// bf16 warp MMA m16n8k16, fp32 accum (sm_80+; tensor pipe on sm_100)
#define MMA16816(c, a, b0, b1) \
    asm volatile("mma.sync.aligned.m16n8k16.row.col.f32.bf16.bf16.f32 " \
        "{%0,%1,%2,%3}, {%4,%5,%6,%7}, {%8,%9}, {%0,%1,%2,%3};" \
        : "+f"((c)[0]), "+f"((c)[1]), "+f"((c)[2]), "+f"((c)[3]) \
        : "r"((a)[0]), "r"((a)[1]), "r"((a)[2]), "r"((a)[3]), "r"(b0), "r"(b1))

// ---------------- weight prep: w[co][ci][9][9] fp32 -> wb[co][tap*256+ci] bf16 hi/lo ----------------
__global__ void prep_w_kernel(const float* __restrict__ w) {
    int k  = blockIdx.x * 256 + threadIdx.x;   // 0..20735 (grid.x = 81)
    int co = blockIdx.y;
    int tap = k >> 8, ci = k & 255;
    float v = w[(size_t)co * 20736 + ci * 81 + tap];
    __nv_bfloat16 h = __float2bfloat16(v);
    size_t dst = (size_t)co * 20736 + k;
    g_wbh[dst] = h;
    g_wbl[dst] = __float2bfloat16(v - __bfloat162float(h));
}

// ---------------- conv1: (B,1,28,28) -> relu -> NHWC bf16 hi/lo (B,20,20,256) ----------------
__global__ __launch_bounds__(256)
void conv1_kernel(const float* __restrict__ x, const float* __restrict__ w,
                  const float* __restrict__ bias) {
    __shared__ float img[784];
    __shared__ float ws[2592];                 // layout [tap][32 co]
    int b = blockIdx.y, co0 = blockIdx.x * 32;
    int tid = threadIdx.x;
    for (int i = tid; i < 784; i += 256) img[i] = x[b * 784 + i];
    for (int i = tid; i < 2592; i += 256) {
        int t = i >> 5, c = i & 31;
        ws[i] = w[(co0 + c) * 81 + t];
    }
    u64 b2[16];
    #pragma unroll
    for (int c = 0; c < 16; c++) b2[c] = pack2(bias[co0 + 2*c], bias[co0 + 2*c + 1]);
    __syncthreads();

    for (int p = tid; p < 400; p += 256) {
        int oy = p / 20, ox = p % 20;
        u64 acc[16];
        #pragma unroll
        for (int c = 0; c < 16; c++) acc[c] = b2[c];
        #pragma unroll 1
        for (int dy = 0; dy < 9; dy++) {
            const float* row = img + (oy + dy) * 28 + ox;
            u64 rr[9];
            #pragma unroll
            for (int dx = 0; dx < 9; dx++) rr[dx] = pack_dup(row[dx]);
            #pragma unroll
            for (int dx = 0; dx < 9; dx++) {
                const u64* wp = (const u64*)(ws + (dy * 9 + dx) * 32);
                #pragma unroll
                for (int c = 0; c < 16; c++) fma2(acc[c], wp[c], rr[dx]);
            }
        }
        size_t base = ((size_t)b * 400 + p) * 256 + co0;
        #pragma unroll
        for (int c = 0; c < 16; c++) {
            float lo, hi; unpack2(acc[c], lo, hi);
            lo = fmaxf(lo, 0.f); hi = fmaxf(hi, 0.f);
            __nv_bfloat16 hl = __float2bfloat16(lo);
            __nv_bfloat16 hh = __float2bfloat16(hi);
            float rl = lo - __bfloat162float(hl);
            float rh = hi - __bfloat162float(hh);
            *reinterpret_cast<__nv_bfloat162*>(&g_h1h[base + 2*c]) = __halves2bfloat162(hl, hh);
            *reinterpret_cast<__nv_bfloat162*>(&g_h1l[base + 2*c]) =
                __halves2bfloat162(__float2bfloat16(rl), __float2bfloat16(rh));
        }
    }
}

// ---------------- caps1 via mma.sync: C[9216,256] = A[9216,20736] @ W^T ----------------
static constexpr int CSTG = 24576;
static constexpr u32 SMEM_C1 = 2 * CSTG;   // 49152 = default limit

__global__ __launch_bounds__(256, 1)
void caps1_mma_kernel(const float* __restrict__ bias) {
    extern __shared__ char smem[];
    u32 sm = smem_u32(smem);
    int tid = threadIdx.x;
    int n0 = blockIdx.x * 128, m0 = blockIdx.y * 128;

    // loader: thread -> (row rw, 16B chunk ch). cp16 moves 16B = 8 bf16.
    int rw = tid >> 1, ch = tid & 1;
    int pl = m0 + rw;
    int pb = pl / 36, prr = pl % 36, loy = prr / 6, lox = prr % 6;
    u32 aPix = (u32)((pb * 20 + 2 * loy) * 20 + 2 * lox) * 256 + ch * 8;
    u32 bRow = (u32)(n0 + rw) * 20736 + ch * 8;
    u32 smOff = (u32)(rw * 48 + ch * 16);

    auto load_stage = [&](int s, int step) {
        u32 base = sm + s * CSTG;
        int tap = step >> 4, ci0 = (step & 15) * 16;
        int dy = tap / 9, dx = tap - dy * 9;
        u32 asrc = aPix + (u32)(dy * 20 + dx) * 256 + ci0;
        u32 bsrc = bRow + (u32)tap * 256 + ci0;
        cp16(base + smOff,         g_h1h + asrc);
        cp16(base + 6144 + smOff,  g_h1l + asrc);
        cp16(base + 12288 + smOff, g_wbh + bsrc);
        cp16(base + 18432 + smOff, g_wbl + bsrc);
        cp_commit();
    };

    int wid = tid >> 5, lane = tid & 31;
    int wm = wid & 3, wn = wid >> 2;               // warp tile: M 32, N 64
    int g = lane >> 2, tc = lane & 3;

    float c[2][8][4];
    #pragma unroll
    for (int i = 0; i < 2; i++)
        #pragma unroll
        for (int j = 0; j < 8; j++)
            #pragma unroll
            for (int q = 0; q < 4; q++) c[i][j][q] = 0.f;

    load_stage(0, 0);

    #pragma unroll 1
    for (int step = 0; step < 1296; step++) {
        int cur = step & 1;
        if (step + 1 < 1296) { load_stage(cur ^ 1, step + 1); CP_WAIT(1); }
        else CP_WAIT(0);
        __syncthreads();

        const u32* Ah = (const u32*)(smem + cur * CSTG);
        const u32* Al = Ah + 1536;
        const u32* Bh = Ah + 3072;
        const u32* Bl = Ah + 4608;
        u32 ah[2][4], al[2][4];
        #pragma unroll
        for (int tm = 0; tm < 2; tm++) {
            int r = wm * 32 + tm * 16 + g;
            ah[tm][0] = Ah[r * 12 + tc];       ah[tm][1] = Ah[(r + 8) * 12 + tc];
            ah[tm][2] = Ah[r * 12 + tc + 4];   ah[tm][3] = Ah[(r + 8) * 12 + tc + 4];
            al[tm][0] = Al[r * 12 + tc];       al[tm][1] = Al[(r + 8) * 12 + tc];
            al[tm][2] = Al[r * 12 + tc + 4];   al[tm][3] = Al[(r + 8) * 12 + tc + 4];
        }
        #pragma unroll
        for (int tn = 0; tn < 8; tn++) {
            int n = wn * 64 + tn * 8 + g;
            u32 bh0 = Bh[n * 12 + tc], bh1 = Bh[n * 12 + tc + 4];
            u32 bl0 = Bl[n * 12 + tc], bl1 = Bl[n * 12 + tc + 4];
            #pragma unroll
            for (int tm = 0; tm < 2; tm++) {
                MMA16816(c[tm][tn], ah[tm], bh0, bh1);
                MMA16816(c[tm][tn], ah[tm], bl0, bl1);
                MMA16816(c[tm][tn], al[tm], bh0, bh1);
            }
        }
        __syncthreads();
    }

    // epilogue: bias + relu -> g_h2[b][co][36]
    #pragma unroll
    for (int tm = 0; tm < 2; tm++) {
        int r0 = m0 + wm * 32 + tm * 16 + g;
        int b0i = r0 / 36, rr0 = r0 % 36;
        int r1 = r0 + 8;
        int b1i = r1 / 36, rr1 = r1 % 36;
        float* d0 = g_h2 + (size_t)b0i * 9216 + rr0;
        float* d1 = g_h2 + (size_t)b1i * 9216 + rr1;
        #pragma unroll
        for (int tn = 0; tn < 8; tn++) {
            int cc = n0 + wn * 64 + tn * 8 + tc * 2;
            float bv0 = bias[cc], bv1 = bias[cc + 1];
            d0[(size_t)cc * 36]       = fmaxf(c[tm][tn][0] + bv0, 0.f);
            d0[(size_t)(cc + 1) * 36] = fmaxf(c[tm][tn][1] + bv1, 0.f);
            d1[(size_t)cc * 36]       = fmaxf(c[tm][tn][2] + bv0, 0.f);
            d1[(size_t)(cc + 1) * 36] = fmaxf(c[tm][tn][3] + bv1, 0.f);
        }
    }
}

// ---------------- u = Wj @ x_tile, warp-per-row (coalesced W reads) ----------------
// grid (256 b, 8 chunks), 256 thr = 8 warps. Warp handles r = chunk*1440 + wid + 8k.
// Lane l holds W[r][4l..4l+3] (one float4, coalesced 512B per warp);
// pairwise shfl reduce gives the 16 outputs (mm = l/2); even lanes store.
__global__ __launch_bounds__(256)
void u_kernel(const float* __restrict__ W) {
    __shared__ float sx[9216];
    int b = blockIdx.x, chunk = blockIdx.y;
    int tid = threadIdx.x, wid = tid >> 5, lane = tid & 31;
    const float* h2b = g_h2 + (size_t)b * 9216;
    for (int i = tid; i < 9216; i += 256) sx[i] = h2b[i];
    __syncthreads();

    int half = lane & 1, mm = lane >> 1;
    float* ub = g_u + (size_t)b * 184320;

    #pragma unroll 1
    for (int k = 0; k < 180; k++) {
        int r = chunk * 1440 + wid + 8 * k;
        float4 w4 = reinterpret_cast<const float4*>(W)[(size_t)r * 32 + lane];
        int qb = r * 8 + half * 4;
        float p;
        {
            int q0 = qb, q1 = qb + 1, q2 = qb + 2, q3 = qb + 3;
            float x0 = sx[(q0 / 360) * 36 + (q0 % 36)];
            float x1 = sx[(q1 / 360) * 36 + (q1 % 36)];
            float x2 = sx[(q2 / 360) * 36 + (q2 % 36)];
            float x3 = sx[(q3 / 360) * 36 + (q3 % 36)];
            p = w4.x * x0 + w4.y * x1 + w4.z * x2 + w4.w * x3;
        }
        float s = p + __shfl_xor_sync(0xFFFFFFFFu, p, 1);
        if (half == 0) ub[(size_t)r * 16 + mm] = s;
    }
}

// ---------------- dynamic routing (3 iters), one block per batch ----------------
__global__ __launch_bounds__(288)
void routing_kernel(const float* __restrict__ y, const float* __restrict__ bias_r,
                    float* __restrict__ out) {
    __shared__ float spart[18 * 160];
    __shared__ float sfull[160];
    __shared__ __align__(16) float sv[160];
    __shared__ float sscale[16];
    int b = blockIdx.x, t = threadIdx.x;
    const float* ub = g_u + (size_t)b * 184320;
    float* sb = g_blog + (size_t)b * 11520;
    int g = t >> 4, m = t & 15;

    for (int iter = 0; iter < 3; ++iter) {
        float acc[10];
        #pragma unroll
        for (int j = 0; j < 10; j++) acc[j] = 0.f;
        int i0 = g * 64;
        for (int i = i0; i < i0 + 64; i++) {
            float c[10];
            if (iter == 0) {
                #pragma unroll
                for (int j = 0; j < 10; j++) c[j] = 0.1f;
            } else {
                float mx = -1e30f;
                #pragma unroll
                for (int j = 0; j < 10; j++) { c[j] = sb[i * 10 + j]; mx = fmaxf(mx, c[j]); }
                float s = 0.f;
                #pragma unroll
                for (int j = 0; j < 10; j++) { c[j] = __expf(c[j] - mx); s += c[j]; }
                float inv = 1.f / s;
                #pragma unroll
                for (int j = 0; j < 10; j++) c[j] *= inv;
            }
            const float* up = ub + (size_t)i * 160 + m;
            #pragma unroll
            for (int j = 0; j < 10; j++) acc[j] += c[j] * up[j * 16];
        }
        #pragma unroll
        for (int j = 0; j < 10; j++) spart[g * 160 + j * 16 + m] = acc[j];
        __syncthreads();

        if (t < 160) {
            float s = bias_r[t];
            #pragma unroll
            for (int g2 = 0; g2 < 18; g2++) s += spart[g2 * 160 + t];
            sfull[t] = s;
        }
        __syncthreads();
        if (t < 10) {
            float n2 = 0.f;
            #pragma unroll
            for (int mm = 0; mm < 16; mm++) { float v = sfull[t * 16 + mm]; n2 += v * v; }
            sscale[t] = (n2 / (1.f + n2)) / sqrtf(n2 + EPSF);
        }
        __syncthreads();
        if (t < 160) sv[t] = sfull[t] * sscale[t >> 4];
        __syncthreads();

        if (iter < 2) {
            for (int idx = t; idx < 11520; idx += 288) {
                int j = idx % 10;
                const float4* up4 = (const float4*)(ub + (size_t)idx * 16);
                const float4* vv4 = (const float4*)(sv + j * 16);
                float d = 0.f;
                #pragma unroll
                for (int q = 0; q < 4; q++) {
                    float4 a = up4[q], v4 = vv4[q];
                    d += a.x * v4.x + a.y * v4.y + a.z * v4.z + a.w * v4.w;
                }
                if (iter == 0) sb[idx] = d; else sb[idx] += d;
            }
        }
        __syncthreads();
    }
    if (t < 10) {
        float n2 = 0.f;
        #pragma unroll
        for (int mm = 0; mm < 16; mm++) { float v = sv[t * 16 + mm]; n2 += v * v; }
        out[b * 10 + t] = sqrtf(n2 + EPSF);
    }
    if (t < 16) {
        float s = 0.f;
        const float* yb = y + b * 10;
        #pragma unroll
        for (int tt = 0; tt < 10; tt++) s += sv[t * 10 + tt] * yb[tt];
        g_masked[b * 16 + t] = s;
    }
}

// ---------------- FC GEMM ----------------
__global__ void gemm_kernel(const float* __restrict__ Wt, const float* __restrict__ bias,
                            float* __restrict__ out, int N, int K, int which) {
    __shared__ float As[16][16];
    __shared__ float Bs[16][17];
    const float* A; float* C;
    if (which == 0)      { A = g_masked; C = g_fc1; }
    else if (which == 1) { A = g_fc1;    C = g_fc2; }
    else                 { A = g_fc2;    C = out + 2560; }
    int tx = threadIdx.x, ty = threadIdx.y;
    int n0 = blockIdx.x * 16, m0 = blockIdx.y * 16;
    float acc = 0.f;
    for (int k0 = 0; k0 < K; k0 += 16) {
        As[ty][tx] = A[(size_t)(m0 + ty) * K + k0 + tx];
        Bs[ty][tx] = Wt[(size_t)(n0 + ty) * K + k0 + tx];
        __syncthreads();
        #pragma unroll
        for (int kk = 0; kk < 16; kk++) acc += As[ty][kk] * Bs[tx][kk];
        __syncthreads();
    }
    acc += bias[n0 + tx];
    if (which == 2) acc = 1.f / (1.f + expf(-acc));
    C[(size_t)(m0 + ty) * N + n0 + tx] = acc;
}

// ---------------- launch ----------------
extern "C" void kernel_launch(void* const* d_in, const int* in_sizes, int n_in,
                              void* d_out, int out_size) {
    (void)in_sizes; (void)n_in; (void)out_size;
    const float* x   = (const float*)d_in[0];
    const float* y   = (const float*)d_in[1];
    const float* c1w = (const float*)d_in[2];
    const float* c1b = (const float*)d_in[3];
    const float* c2w = (const float*)d_in[4];
    const float* c2b = (const float*)d_in[5];
    const float* W   = (const float*)d_in[6];
    const float* br  = (const float*)d_in[7];
    const float* f1w = (const float*)d_in[8];
    const float* f1b = (const float*)d_in[9];
    const float* f2w = (const float*)d_in[10];
    const float* f2b = (const float*)d_in[11];
    const float* f3w = (const float*)d_in[12];
    const float* f3b = (const float*)d_in[13];
    float* out = (float*)d_out;

    prep_w_kernel<<<dim3(81, 256), 256>>>(c2w);
    conv1_kernel<<<dim3(8, 256), 256>>>(x, c1w, c1b);
    caps1_mma_kernel<<<dim3(2, 72), 256, SMEM_C1>>>(c2b);
    u_kernel<<<dim3(256, 8), 256>>>(W);
    routing_kernel<<<256, 288>>>(y, br, out);
    gemm_kernel<<<dim3(32, 16), dim3(16, 16)>>>(f1w, f1b, out, 512, 16, 0);
    gemm_kernel<<<dim3(64, 16), dim3(16, 16)>>>(f2w, f2b, out, 1024, 512, 1);
    gemm_kernel<<<dim3(49, 16), dim3(16, 16)>>>(f3w, f3b, out, 784, 1024, 2);
}

// round 8
// speedup vs baseline: 1.8940x; 1.0530x over previous
#include <cuda_runtime.h>
#include <cuda_bf16.h>
#include <cstdint>

#define EPSF 1e-9f
typedef unsigned long long u64;
typedef unsigned int u32;

// ---------------- persistent device scratch ----------------
__device__ __nv_bfloat16 g_h1h[256*400*256];   // conv1 out NHWC, bf16 hi  52MB
__device__ __nv_bfloat16 g_h1l[256*400*256];   // conv1 out NHWC, bf16 lo  52MB
__device__ __nv_bfloat16 g_wbh[256*20736];     // caps1 W [co][tap*256+ci] hi
__device__ __nv_bfloat16 g_wbl[256*20736];     // caps1 W lo
__device__ float g_h2[256*256*36];             // caps1 out (relu'd)  [b][co][36]
__device__ float g_u[256u*1152*10*16];         // prediction vectors  189MB
__device__ float g_blog[256*11520];            // routing logits
__device__ float g_masked[256*16];
__device__ float g_fc1[256*512];
__device__ float g_fc2[256*1024];

// ---------------- helpers ----------------
__device__ __forceinline__ void fma2(u64& acc, u64 a, u64 b) {
    asm("fma.rn.f32x2 %0, %1, %2, %0;" : "+l"(acc) : "l"(a), "l"(b));
}
__device__ __forceinline__ u64 pack2(float lo, float hi) {
    u64 r; unsigned il = __float_as_uint(lo), ih = __float_as_uint(hi);
    asm("mov.b64 %0, {%1, %2};" : "=l"(r) : "r"(il), "r"(ih));
    return r;
}
__device__ __forceinline__ u64 pack_dup(float v) {
    u64 r; unsigned iv = __float_as_uint(v);
    asm("mov.b64 %0, {%1, %1};" : "=l"(r) : "r"(iv));
    return r;
}
__device__ __forceinline__ void unpack2(u64 v, float& lo, float& hi) {
    asm("mov.b64 {%0, %1}, %2;" : "=f"(lo), "=f"(hi) : "l"(v));
}
__device__ __forceinline__ u32 smem_u32(const void* p) {
    u32 a;
    asm("{ .reg .u64 t; cvta.to.shared.u64 t, %1; cvt.u32.u64 %0, t; }" : "=r"(a) : "l"(p));
    return a;
}
__device__ __forceinline__ void cp16(u32 dst, const void* src) {
    asm volatile("cp.async.cg.shared.global [%0], [%1], 16;" :: "r"(dst), "l"(src) : "memory");
}
__device__ __forceinline__ void cp_commit() { asm volatile("cp.async.commit_group;" ::: "memory"); }
#define CP_WAIT(n) asm volatile("cp.async.wait_group %0;" :: "n"(n) : "memory")

// bf16 warp MMA m16n8k16, fp32 accum (sm_80+; tensor pipe on sm_100)
#define MMA16816(c, a, b0, b1) \
    asm volatile("mma.sync.aligned.m16n8k16.row.col.f32.bf16.bf16.f32 " \
        "{%0,%1,%2,%3}, {%4,%5,%6,%7}, {%8,%9}, {%0,%1,%2,%3};" \
        : "+f"((c)[0]), "+f"((c)[1]), "+f"((c)[2]), "+f"((c)[3]) \
        : "r"((a)[0]), "r"((a)[1]), "r"((a)[2]), "r"((a)[3]), "r"(b0), "r"(b1))

// ---------------- weight prep: w[co][ci][9][9] fp32 -> wb[co][tap*256+ci] bf16 hi/lo ----------------
__global__ void prep_w_kernel(const float* __restrict__ w) {
    int k  = blockIdx.x * 256 + threadIdx.x;   // 0..20735 (grid.x = 81)
    int co = blockIdx.y;
    int tap = k >> 8, ci = k & 255;
    float v = w[(size_t)co * 20736 + ci * 81 + tap];
    __nv_bfloat16 h = __float2bfloat16(v);
    size_t dst = (size_t)co * 20736 + k;
    g_wbh[dst] = h;
    g_wbl[dst] = __float2bfloat16(v - __bfloat162float(h));
}

// ---------------- conv1: (B,1,28,28) -> relu -> NHWC bf16 hi/lo (B,20,20,256) ----------------
__global__ __launch_bounds__(256)
void conv1_kernel(const float* __restrict__ x, const float* __restrict__ w,
                  const float* __restrict__ bias) {
    __shared__ float img[784];
    __shared__ float ws[2592];                 // layout [tap][32 co]
    int b = blockIdx.y, co0 = blockIdx.x * 32;
    int tid = threadIdx.x;
    for (int i = tid; i < 784; i += 256) img[i] = x[b * 784 + i];
    for (int i = tid; i < 2592; i += 256) {
        int t = i >> 5, c = i & 31;
        ws[i] = w[(co0 + c) * 81 + t];
    }
    u64 b2[16];
    #pragma unroll
    for (int c = 0; c < 16; c++) b2[c] = pack2(bias[co0 + 2*c], bias[co0 + 2*c + 1]);
    __syncthreads();

    for (int p = tid; p < 400; p += 256) {
        int oy = p / 20, ox = p % 20;
        u64 acc[16];
        #pragma unroll
        for (int c = 0; c < 16; c++) acc[c] = b2[c];
        #pragma unroll 1
        for (int dy = 0; dy < 9; dy++) {
            const float* row = img + (oy + dy) * 28 + ox;
            u64 rr[9];
            #pragma unroll
            for (int dx = 0; dx < 9; dx++) rr[dx] = pack_dup(row[dx]);
            #pragma unroll
            for (int dx = 0; dx < 9; dx++) {
                const u64* wp = (const u64*)(ws + (dy * 9 + dx) * 32);
                #pragma unroll
                for (int c = 0; c < 16; c++) fma2(acc[c], wp[c], rr[dx]);
            }
        }
        size_t base = ((size_t)b * 400 + p) * 256 + co0;
        #pragma unroll
        for (int c = 0; c < 16; c++) {
            float lo, hi; unpack2(acc[c], lo, hi);
            lo = fmaxf(lo, 0.f); hi = fmaxf(hi, 0.f);
            __nv_bfloat16 hl = __float2bfloat16(lo);
            __nv_bfloat16 hh = __float2bfloat16(hi);
            float rl = lo - __bfloat162float(hl);
            float rh = hi - __bfloat162float(hh);
            *reinterpret_cast<__nv_bfloat162*>(&g_h1h[base + 2*c]) = __halves2bfloat162(hl, hh);
            *reinterpret_cast<__nv_bfloat162*>(&g_h1l[base + 2*c]) =
                __halves2bfloat162(__float2bfloat16(rl), __float2bfloat16(rh));
        }
    }
}

// ---------------- caps1 via mma.sync: C[9216,256] = A[9216,20736] @ W^T ----------------
// 128 threads (4 warps, 2x2), CTA tile M=64 x N=128, 2 CTAs/SM for latency overlap.
// K-step 16, 1296 steps, bf16 hi/lo 3-MMA split, 2-stage cp.async.
// stage: Ah 3K | Al 3K | Bh 6K | Bl 6K (48B pitch rows) = 18KB; x2 = 36KB.
static constexpr int CSTG = 18432;
static constexpr u32 SMEM_C1 = 2 * CSTG;   // 36864 < 48KB default

__global__ __launch_bounds__(128, 2)
void caps1_mma_kernel(const float* __restrict__ bias) {
    extern __shared__ char smem[];
    u32 sm = smem_u32(smem);
    int tid = threadIdx.x;
    int n0 = blockIdx.x * 128, m0 = blockIdx.y * 64;

    // loader: rw = tid>>1 (0..63), ch = tid&1 (16B chunk = 8 bf16)
    int rw = tid >> 1, ch = tid & 1;
    int pl = m0 + rw;
    int pb = pl / 36, prr = pl % 36, loy = prr / 6, lox = prr % 6;
    u32 aPix  = (u32)((pb * 20 + 2 * loy) * 20 + 2 * lox) * 256 + ch * 8;
    u32 bRow0 = (u32)(n0 + rw) * 20736 + ch * 8;
    u32 bRow1 = (u32)(n0 + rw + 64) * 20736 + ch * 8;
    u32 aOff  = (u32)(rw * 48 + ch * 16);
    u32 bOff0 = aOff;
    u32 bOff1 = (u32)((rw + 64) * 48 + ch * 16);

    auto load_stage = [&](int s, int step) {
        u32 base = sm + s * CSTG;
        int tap = step >> 4, ci0 = (step & 15) * 16;
        int dy = tap / 9, dx = tap - dy * 9;
        u32 asrc = aPix + (u32)(dy * 20 + dx) * 256 + ci0;
        u32 bs = (u32)tap * 256 + ci0;
        cp16(base + aOff,          g_h1h + asrc);
        cp16(base + 3072 + aOff,   g_h1l + asrc);
        cp16(base + 6144 + bOff0,  g_wbh + bRow0 + bs);
        cp16(base + 6144 + bOff1,  g_wbh + bRow1 + bs);
        cp16(base + 12288 + bOff0, g_wbl + bRow0 + bs);
        cp16(base + 12288 + bOff1, g_wbl + bRow1 + bs);
        cp_commit();
    };

    int wid = tid >> 5, lane = tid & 31;
    int wm = wid & 1, wn = wid >> 1;               // warp tile: M 32, N 64
    int g = lane >> 2, tc = lane & 3;

    float c[2][8][4];
    #pragma unroll
    for (int i = 0; i < 2; i++)
        #pragma unroll
        for (int j = 0; j < 8; j++)
            #pragma unroll
            for (int q = 0; q < 4; q++) c[i][j][q] = 0.f;

    load_stage(0, 0);

    #pragma unroll 1
    for (int step = 0; step < 1296; step++) {
        int cur = step & 1;
        if (step + 1 < 1296) { load_stage(cur ^ 1, step + 1); CP_WAIT(1); }
        else CP_WAIT(0);
        __syncthreads();

        const u32* Ah = (const u32*)(smem + cur * CSTG);
        const u32* Al = Ah + 768;      // +3072B
        const u32* Bh = Ah + 1536;     // +6144B
        const u32* Bl = Ah + 3072;     // +12288B
        u32 ah[2][4], al[2][4];
        #pragma unroll
        for (int tm = 0; tm < 2; tm++) {
            int r = wm * 32 + tm * 16 + g;
            ah[tm][0] = Ah[r * 12 + tc];       ah[tm][1] = Ah[(r + 8) * 12 + tc];
            ah[tm][2] = Ah[r * 12 + tc + 4];   ah[tm][3] = Ah[(r + 8) * 12 + tc + 4];
            al[tm][0] = Al[r * 12 + tc];       al[tm][1] = Al[(r + 8) * 12 + tc];
            al[tm][2] = Al[r * 12 + tc + 4];   al[tm][3] = Al[(r + 8) * 12 + tc + 4];
        }
        #pragma unroll
        for (int tn = 0; tn < 8; tn++) {
            int n = wn * 64 + tn * 8 + g;
            u32 bh0 = Bh[n * 12 + tc], bh1 = Bh[n * 12 + tc + 4];
            u32 bl0 = Bl[n * 12 + tc], bl1 = Bl[n * 12 + tc + 4];
            #pragma unroll
            for (int tm = 0; tm < 2; tm++) {
                MMA16816(c[tm][tn], ah[tm], bh0, bh1);
                MMA16816(c[tm][tn], ah[tm], bl0, bl1);
                MMA16816(c[tm][tn], al[tm], bh0, bh1);
            }
        }
        __syncthreads();
    }

    // epilogue: bias + relu -> g_h2[b][co][36]
    #pragma unroll
    for (int tm = 0; tm < 2; tm++) {
        int r0 = m0 + wm * 32 + tm * 16 + g;
        int b0i = r0 / 36, rr0 = r0 % 36;
        int r1 = r0 + 8;
        int b1i = r1 / 36, rr1 = r1 % 36;
        float* d0 = g_h2 + (size_t)b0i * 9216 + rr0;
        float* d1 = g_h2 + (size_t)b1i * 9216 + rr1;
        #pragma unroll
        for (int tn = 0; tn < 8; tn++) {
            int cc = n0 + wn * 64 + tn * 8 + tc * 2;
            float bv0 = bias[cc], bv1 = bias[cc + 1];
            d0[(size_t)cc * 36]       = fmaxf(c[tm][tn][0] + bv0, 0.f);
            d0[(size_t)(cc + 1) * 36] = fmaxf(c[tm][tn][1] + bv1, 0.f);
            d1[(size_t)cc * 36]       = fmaxf(c[tm][tn][2] + bv0, 0.f);
            d1[(size_t)(cc + 1) * 36] = fmaxf(c[tm][tn][3] + bv1, 0.f);
        }
    }
}

// ---------------- u = Wj @ x_tile, warp-per-row ----------------
// q..q+3 (q%4==0) never cross a %36 or /360 boundary -> h2 indices consecutive,
// so one div/mod + one LDS.128 replaces 4 scalar gathers.
__global__ __launch_bounds__(256)
void u_kernel(const float* __restrict__ W) {
    __shared__ __align__(16) float sx[9216];
    int b = blockIdx.x, chunk = blockIdx.y;
    int tid = threadIdx.x, wid = tid >> 5, lane = tid & 31;
    const float* h2b = g_h2 + (size_t)b * 9216;
    for (int i = tid; i < 9216; i += 256) sx[i] = h2b[i];
    __syncthreads();

    int half = lane & 1, mm = lane >> 1;
    float* ub = g_u + (size_t)b * 184320;

    #pragma unroll 4
    for (int k = 0; k < 180; k++) {
        int r = chunk * 1440 + wid + 8 * k;
        float4 w4 = reinterpret_cast<const float4*>(W)[(size_t)r * 32 + lane];
        int qb = r * 8 + half * 4;
        int base = (qb / 360) * 36 + (qb % 36);
        float4 x4 = *reinterpret_cast<const float4*>(&sx[base]);
        float p = w4.x * x4.x + w4.y * x4.y + w4.z * x4.z + w4.w * x4.w;
        float s = p + __shfl_xor_sync(0xFFFFFFFFu, p, 1);
        if (half == 0) ub[(size_t)r * 16 + mm] = s;
    }
}

// ---------------- dynamic routing (3 iters), one block per batch ----------------
__global__ __launch_bounds__(288)
void routing_kernel(const float* __restrict__ y, const float* __restrict__ bias_r,
                    float* __restrict__ out) {
    __shared__ float spart[18 * 160];
    __shared__ float sfull[160];
    __shared__ __align__(16) float sv[160];
    __shared__ float sscale[16];
    int b = blockIdx.x, t = threadIdx.x;
    const float* ub = g_u + (size_t)b * 184320;
    float* sb = g_blog + (size_t)b * 11520;
    int g = t >> 4, m = t & 15;

    for (int iter = 0; iter < 3; ++iter) {
        float acc[10];
        #pragma unroll
        for (int j = 0; j < 10; j++) acc[j] = 0.f;
        int i0 = g * 64;
        for (int i = i0; i < i0 + 64; i++) {
            float c[10];
            if (iter == 0) {
                #pragma unroll
                for (int j = 0; j < 10; j++) c[j] = 0.1f;
            } else {
                float mx = -1e30f;
                #pragma unroll
                for (int j = 0; j < 10; j++) { c[j] = sb[i * 10 + j]; mx = fmaxf(mx, c[j]); }
                float s = 0.f;
                #pragma unroll
                for (int j = 0; j < 10; j++) { c[j] = __expf(c[j] - mx); s += c[j]; }
                float inv = 1.f / s;
                #pragma unroll
                for (int j = 0; j < 10; j++) c[j] *= inv;
            }
            const float* up = ub + (size_t)i * 160 + m;
            #pragma unroll
            for (int j = 0; j < 10; j++) acc[j] += c[j] * up[j * 16];
        }
        #pragma unroll
        for (int j = 0; j < 10; j++) spart[g * 160 + j * 16 + m] = acc[j];
        __syncthreads();

        if (t < 160) {
            float s = bias_r[t];
            #pragma unroll
            for (int g2 = 0; g2 < 18; g2++) s += spart[g2 * 160 + t];
            sfull[t] = s;
        }
        __syncthreads();
        if (t < 10) {
            float n2 = 0.f;
            #pragma unroll
            for (int mm = 0; mm < 16; mm++) { float v = sfull[t * 16 + mm]; n2 += v * v; }
            sscale[t] = (n2 / (1.f + n2)) / sqrtf(n2 + EPSF);
        }
        __syncthreads();
        if (t < 160) sv[t] = sfull[t] * sscale[t >> 4];
        __syncthreads();

        if (iter < 2) {
            for (int idx = t; idx < 11520; idx += 288) {
                int j = idx % 10;
                const float4* up4 = (const float4*)(ub + (size_t)idx * 16);
                const float4* vv4 = (const float4*)(sv + j * 16);
                float d = 0.f;
                #pragma unroll
                for (int q = 0; q < 4; q++) {
                    float4 a = up4[q], v4 = vv4[q];
                    d += a.x * v4.x + a.y * v4.y + a.z * v4.z + a.w * v4.w;
                }
                if (iter == 0) sb[idx] = d; else sb[idx] += d;
            }
        }
        __syncthreads();
    }
    if (t < 10) {
        float n2 = 0.f;
        #pragma unroll
        for (int mm = 0; mm < 16; mm++) { float v = sv[t * 16 + mm]; n2 += v * v; }
        out[b * 10 + t] = sqrtf(n2 + EPSF);
    }
    if (t < 16) {
        float s = 0.f;
        const float* yb = y + b * 10;
        #pragma unroll
        for (int tt = 0; tt < 10; tt++) s += sv[t * 10 + tt] * yb[tt];
        g_masked[b * 16 + t] = s;
    }
}

// ---------------- FC GEMM ----------------
__global__ void gemm_kernel(const float* __restrict__ Wt, const float* __restrict__ bias,
                            float* __restrict__ out, int N, int K, int which) {
    __shared__ float As[16][16];
    __shared__ float Bs[16][17];
    const float* A; float* C;
    if (which == 0)      { A = g_masked; C = g_fc1; }
    else if (which == 1) { A = g_fc1;    C = g_fc2; }
    else                 { A = g_fc2;    C = out + 2560; }
    int tx = threadIdx.x, ty = threadIdx.y;
    int n0 = blockIdx.x * 16, m0 = blockIdx.y * 16;
    float acc = 0.f;
    for (int k0 = 0; k0 < K; k0 += 16) {
        As[ty][tx] = A[(size_t)(m0 + ty) * K + k0 + tx];
        Bs[ty][tx] = Wt[(size_t)(n0 + ty) * K + k0 + tx];
        __syncthreads();
        #pragma unroll
        for (int kk = 0; kk < 16; kk++) acc += As[ty][kk] * Bs[tx][kk];
        __syncthreads();
    }
    acc += bias[n0 + tx];
    if (which == 2) acc = 1.f / (1.f + expf(-acc));
    C[(size_t)(m0 + ty) * N + n0 + tx] = acc;
}

// ---------------- launch ----------------
extern "C" void kernel_launch(void* const* d_in, const int* in_sizes, int n_in,
                              void* d_out, int out_size) {
    (void)in_sizes; (void)n_in; (void)out_size;
    const float* x   = (const float*)d_in[0];
    const float* y   = (const float*)d_in[1];
    const float* c1w = (const float*)d_in[2];
    const float* c1b = (const float*)d_in[3];
    const float* c2w = (const float*)d_in[4];
    const float* c2b = (const float*)d_in[5];
    const float* W   = (const float*)d_in[6];
    const float* br  = (const float*)d_in[7];
    const float* f1w = (const float*)d_in[8];
    const float* f1b = (const float*)d_in[9];
    const float* f2w = (const float*)d_in[10];
    const float* f2b = (const float*)d_in[11];
    const float* f3w = (const float*)d_in[12];
    const float* f3b = (const float*)d_in[13];
    float* out = (float*)d_out;

    prep_w_kernel<<<dim3(81, 256), 256>>>(c2w);
    conv1_kernel<<<dim3(8, 256), 256>>>(x, c1w, c1b);
    caps1_mma_kernel<<<dim3(2, 144), 128, SMEM_C1>>>(c2b);
    u_kernel<<<dim3(256, 8), 256>>>(W);
    routing_kernel<<<256, 288>>>(y, br, out);
    gemm_kernel<<<dim3(32, 16), dim3(16, 16)>>>(f1w, f1b, out, 512, 16, 0);
    gemm_kernel<<<dim3(64, 16), dim3(16, 16)>>>(f2w, f2b, out, 1024, 512, 1);
    gemm_kernel<<<dim3(49, 16), dim3(16, 16)>>>(f3w, f3b, out, 784, 1024, 2);
}

// round 9
// speedup vs baseline: 2.4847x; 1.3118x over previous
#include <cuda_runtime.h>
#include <cuda_fp16.h>
#include <cstdint>

#define EPSF 1e-9f
typedef unsigned long long u64;
typedef unsigned int u32;

// ---------------- persistent device scratch ----------------
__device__ __half g_h1h[256*400*256];          // conv1 out NHWC, fp16 hi  52MB
__device__ __half g_h1l[256*400*256];          // conv1 out NHWC, fp16 residual
__device__ __half g_wh[256*20736];             // caps1 W [co][tap*256+ci] fp16
__device__ float g_h2[256*256*36];             // caps1 out (relu'd)  [b][co][36]
__device__ float g_u[256u*1152*10*16];         // prediction vectors  189MB
__device__ float g_blog[256*11520];            // routing logits
__device__ float g_masked[256*16];
__device__ float g_fc1[256*512];
__device__ float g_fc2[256*1024];

// ---------------- helpers ----------------
__device__ __forceinline__ void fma2(u64& acc, u64 a, u64 b) {
    asm("fma.rn.f32x2 %0, %1, %2, %0;" : "+l"(acc) : "l"(a), "l"(b));
}
__device__ __forceinline__ u64 pack2(float lo, float hi) {
    u64 r; unsigned il = __float_as_uint(lo), ih = __float_as_uint(hi);
    asm("mov.b64 %0, {%1, %2};" : "=l"(r) : "r"(il), "r"(ih));
    return r;
}
__device__ __forceinline__ u64 pack_dup(float v) {
    u64 r; unsigned iv = __float_as_uint(v);
    asm("mov.b64 %0, {%1, %1};" : "=l"(r) : "r"(iv));
    return r;
}
__device__ __forceinline__ void unpack2(u64 v, float& lo, float& hi) {
    asm("mov.b64 {%0, %1}, %2;" : "=f"(lo), "=f"(hi) : "l"(v));
}
__device__ __forceinline__ u32 smem_u32(const void* p) {
    u32 a;
    asm("{ .reg .u64 t; cvta.to.shared.u64 t, %1; cvt.u32.u64 %0, t; }" : "=r"(a) : "l"(p));
    return a;
}
__device__ __forceinline__ void cp16(u32 dst, const void* src) {
    asm volatile("cp.async.cg.shared.global [%0], [%1], 16;" :: "r"(dst), "l"(src) : "memory");
}
__device__ __forceinline__ void cp_commit() { asm volatile("cp.async.commit_group;" ::: "memory"); }
#define CP_WAIT(n) asm volatile("cp.async.wait_group %0;" :: "n"(n) : "memory")

// fp16 warp MMA m16n8k16, fp32 accum
#define MMAF16(c, a, b0, b1) \
    asm volatile("mma.sync.aligned.m16n8k16.row.col.f32.f16.f16.f32 " \
        "{%0,%1,%2,%3}, {%4,%5,%6,%7}, {%8,%9}, {%0,%1,%2,%3};" \
        : "+f"((c)[0]), "+f"((c)[1]), "+f"((c)[2]), "+f"((c)[3]) \
        : "r"((a)[0]), "r"((a)[1]), "r"((a)[2]), "r"((a)[3]), "r"(b0), "r"(b1))

// ---------------- weight prep: w[co][ci][9][9] fp32 -> g_wh[co][tap*256+ci] fp16 ----------------
__global__ void prep_w_kernel(const float* __restrict__ w) {
    int k  = blockIdx.x * 256 + threadIdx.x;   // 0..20735 (grid.x = 81)
    int co = blockIdx.y;
    int tap = k >> 8, ci = k & 255;
    g_wh[(size_t)co * 20736 + k] = __float2half(w[(size_t)co * 20736 + ci * 81 + tap]);
}

// ---------------- conv1: (B,1,28,28) -> relu -> NHWC fp16 hi/lo (B,20,20,256) ----------------
__global__ __launch_bounds__(256)
void conv1_kernel(const float* __restrict__ x, const float* __restrict__ w,
                  const float* __restrict__ bias) {
    __shared__ float img[784];
    __shared__ float ws[2592];                 // layout [tap][32 co]
    int b = blockIdx.y, co0 = blockIdx.x * 32;
    int tid = threadIdx.x;
    for (int i = tid; i < 784; i += 256) img[i] = x[b * 784 + i];
    for (int i = tid; i < 2592; i += 256) {
        int t = i >> 5, c = i & 31;
        ws[i] = w[(co0 + c) * 81 + t];
    }
    u64 b2[16];
    #pragma unroll
    for (int c = 0; c < 16; c++) b2[c] = pack2(bias[co0 + 2*c], bias[co0 + 2*c + 1]);
    __syncthreads();

    for (int p = tid; p < 400; p += 256) {
        int oy = p / 20, ox = p % 20;
        u64 acc[16];
        #pragma unroll
        for (int c = 0; c < 16; c++) acc[c] = b2[c];
        #pragma unroll 1
        for (int dy = 0; dy < 9; dy++) {
            const float* row = img + (oy + dy) * 28 + ox;
            u64 rr[9];
            #pragma unroll
            for (int dx = 0; dx < 9; dx++) rr[dx] = pack_dup(row[dx]);
            #pragma unroll
            for (int dx = 0; dx < 9; dx++) {
                const u64* wp = (const u64*)(ws + (dy * 9 + dx) * 32);
                #pragma unroll
                for (int c = 0; c < 16; c++) fma2(acc[c], wp[c], rr[dx]);
            }
        }
        size_t base = ((size_t)b * 400 + p) * 256 + co0;
        #pragma unroll
        for (int c = 0; c < 16; c++) {
            float lo, hi; unpack2(acc[c], lo, hi);
            lo = fmaxf(lo, 0.f); hi = fmaxf(hi, 0.f);
            __half hl = __float2half(lo);
            __half hh = __float2half(hi);
            float rl = lo - __half2float(hl);
            float rh = hi - __half2float(hh);
            *reinterpret_cast<__half2*>(&g_h1h[base + 2*c]) = __halves2half2(hl, hh);
            *reinterpret_cast<__half2*>(&g_h1l[base + 2*c]) =
                __halves2half2(__float2half(rl), __float2half(rh));
        }
    }
}

// ---------------- caps1 via mma.sync fp16 2-split: C[9216,256] = A[9216,20736] @ W^T ----------------
// 128 threads (4 warps 2x2), CTA tile M=64 x N=128, 2 CTAs/SM.
// K-step 16, 1296 steps, A = fp16 hi+lo (2 MMAs), B = fp16 only.
// stage: Ah 3K | Al 3K | Bh 6K (48B pitch rows) = 12KB; 3 stages = 36KB.
static constexpr int CSTG = 12288;
static constexpr u32 SMEM_C1 = 3 * CSTG;   // 36864 < 48KB default

__global__ __launch_bounds__(128, 2)
void caps1_mma_kernel(const float* __restrict__ bias) {
    extern __shared__ char smem[];
    u32 sm = smem_u32(smem);
    int tid = threadIdx.x;
    int n0 = blockIdx.x * 128, m0 = blockIdx.y * 64;

    // loader: rw = tid>>1 (0..63), ch = tid&1 (16B chunk = 8 fp16)
    int rw = tid >> 1, ch = tid & 1;
    int pl = m0 + rw;
    int pb = pl / 36, prr = pl % 36, loy = prr / 6, lox = prr % 6;
    u32 aPix  = (u32)((pb * 20 + 2 * loy) * 20 + 2 * lox) * 256 + ch * 8;
    u32 bRow0 = (u32)(n0 + rw) * 20736 + ch * 8;
    u32 bRow1 = (u32)(n0 + rw + 64) * 20736 + ch * 8;
    u32 aOff  = (u32)(rw * 48 + ch * 16);
    u32 bOff0 = aOff;
    u32 bOff1 = (u32)((rw + 64) * 48 + ch * 16);

    auto load_stage = [&](int s, int step) {
        u32 base = sm + s * CSTG;
        int tap = step >> 4, ci0 = (step & 15) * 16;
        int dy = tap / 9, dx = tap - dy * 9;
        u32 asrc = aPix + (u32)(dy * 20 + dx) * 256 + ci0;
        u32 bs = (u32)tap * 256 + ci0;
        cp16(base + aOff,         g_h1h + asrc);
        cp16(base + 3072 + aOff,  g_h1l + asrc);
        cp16(base + 6144 + bOff0, g_wh + bRow0 + bs);
        cp16(base + 6144 + bOff1, g_wh + bRow1 + bs);
        cp_commit();
    };

    int wid = tid >> 5, lane = tid & 31;
    int wm = wid & 1, wn = wid >> 1;               // warp tile: M 32, N 64
    int g = lane >> 2, tc = lane & 3;

    float c[2][8][4];
    #pragma unroll
    for (int i = 0; i < 2; i++)
        #pragma unroll
        for (int j = 0; j < 8; j++)
            #pragma unroll
            for (int q = 0; q < 4; q++) c[i][j][q] = 0.f;

    load_stage(0, 0);
    load_stage(1, 1);

    #pragma unroll 1
    for (int step = 0; step < 1296; step++) {
        int cur = step % 3;
        if (step + 1 < 1296) { CP_WAIT(1); } else { CP_WAIT(0); }
        __syncthreads();                       // stage cur visible; stage (cur+2)%3 free
        if (step + 2 < 1296) load_stage((step + 2) % 3, step + 2);

        const u32* Ah = (const u32*)(smem + cur * CSTG);
        const u32* Al = Ah + 768;      // +3072B
        const u32* Bh = Ah + 1536;     // +6144B
        u32 ah[2][4], al[2][4];
        #pragma unroll
        for (int tm = 0; tm < 2; tm++) {
            int r = wm * 32 + tm * 16 + g;
            ah[tm][0] = Ah[r * 12 + tc];       ah[tm][1] = Ah[(r + 8) * 12 + tc];
            ah[tm][2] = Ah[r * 12 + tc + 4];   ah[tm][3] = Ah[(r + 8) * 12 + tc + 4];
            al[tm][0] = Al[r * 12 + tc];       al[tm][1] = Al[(r + 8) * 12 + tc];
            al[tm][2] = Al[r * 12 + tc + 4];   al[tm][3] = Al[(r + 8) * 12 + tc + 4];
        }
        #pragma unroll
        for (int tn = 0; tn < 8; tn++) {
            int n = wn * 64 + tn * 8 + g;
            u32 bh0 = Bh[n * 12 + tc], bh1 = Bh[n * 12 + tc + 4];
            #pragma unroll
            for (int tm = 0; tm < 2; tm++) {
                MMAF16(c[tm][tn], ah[tm], bh0, bh1);
                MMAF16(c[tm][tn], al[tm], bh0, bh1);
            }
        }
    }
    __syncthreads();

    // epilogue: bias + relu -> g_h2[b][co][36]
    #pragma unroll
    for (int tm = 0; tm < 2; tm++) {
        int r0 = m0 + wm * 32 + tm * 16 + g;
        int b0i = r0 / 36, rr0 = r0 % 36;
        int r1 = r0 + 8;
        int b1i = r1 / 36, rr1 = r1 % 36;
        float* d0 = g_h2 + (size_t)b0i * 9216 + rr0;
        float* d1 = g_h2 + (size_t)b1i * 9216 + rr1;
        #pragma unroll
        for (int tn = 0; tn < 8; tn++) {
            int cc = n0 + wn * 64 + tn * 8 + tc * 2;
            float bv0 = bias[cc], bv1 = bias[cc + 1];
            d0[(size_t)cc * 36]       = fmaxf(c[tm][tn][0] + bv0, 0.f);
            d0[(size_t)(cc + 1) * 36] = fmaxf(c[tm][tn][1] + bv1, 0.f);
            d1[(size_t)cc * 36]       = fmaxf(c[tm][tn][2] + bv0, 0.f);
            d1[(size_t)(cc + 1) * 36] = fmaxf(c[tm][tn][3] + bv1, 0.f);
        }
    }
}

// ---------------- u = Wj @ x_tile, warp-per-row ----------------
__global__ __launch_bounds__(256)
void u_kernel(const float* __restrict__ W) {
    __shared__ __align__(16) float sx[9216];
    int b = blockIdx.x, chunk = blockIdx.y;
    int tid = threadIdx.x, wid = tid >> 5, lane = tid & 31;
    const float* h2b = g_h2 + (size_t)b * 9216;
    for (int i = tid; i < 9216; i += 256) sx[i] = h2b[i];
    __syncthreads();

    int half = lane & 1, mm = lane >> 1;
    float* ub = g_u + (size_t)b * 184320;

    #pragma unroll 4
    for (int k = 0; k < 180; k++) {
        int r = chunk * 1440 + wid + 8 * k;
        float4 w4 = reinterpret_cast<const float4*>(W)[(size_t)r * 32 + lane];
        int qb = r * 8 + half * 4;
        int base = (qb / 360) * 36 + (qb % 36);
        float4 x4 = *reinterpret_cast<const float4*>(&sx[base]);
        float p = w4.x * x4.x + w4.y * x4.y + w4.z * x4.z + w4.w * x4.w;
        float s = p + __shfl_xor_sync(0xFFFFFFFFu, p, 1);
        if (half == 0) ub[(size_t)r * 16 + mm] = s;
    }
}

// ---------------- dynamic routing (3 iters), one block per batch ----------------
__global__ __launch_bounds__(288)
void routing_kernel(const float* __restrict__ y, const float* __restrict__ bias_r,
                    float* __restrict__ out) {
    __shared__ float spart[18 * 160];
    __shared__ float sfull[160];
    __shared__ __align__(16) float sv[160];
    __shared__ float sscale[16];
    int b = blockIdx.x, t = threadIdx.x;
    const float* ub = g_u + (size_t)b * 184320;
    float* sb = g_blog + (size_t)b * 11520;
    int g = t >> 4, m = t & 15;

    for (int iter = 0; iter < 3; ++iter) {
        float acc[10];
        #pragma unroll
        for (int j = 0; j < 10; j++) acc[j] = 0.f;
        int i0 = g * 64;
        for (int i = i0; i < i0 + 64; i++) {
            float c[10];
            if (iter == 0) {
                #pragma unroll
                for (int j = 0; j < 10; j++) c[j] = 0.1f;
            } else {
                float mx = -1e30f;
                #pragma unroll
                for (int j = 0; j < 10; j++) { c[j] = sb[i * 10 + j]; mx = fmaxf(mx, c[j]); }
                float s = 0.f;
                #pragma unroll
                for (int j = 0; j < 10; j++) { c[j] = __expf(c[j] - mx); s += c[j]; }
                float inv = 1.f / s;
                #pragma unroll
                for (int j = 0; j < 10; j++) c[j] *= inv;
            }
            const float* up = ub + (size_t)i * 160 + m;
            #pragma unroll
            for (int j = 0; j < 10; j++) acc[j] += c[j] * up[j * 16];
        }
        #pragma unroll
        for (int j = 0; j < 10; j++) spart[g * 160 + j * 16 + m] = acc[j];
        __syncthreads();

        if (t < 160) {
            float s = bias_r[t];
            #pragma unroll
            for (int g2 = 0; g2 < 18; g2++) s += spart[g2 * 160 + t];
            sfull[t] = s;
        }
        __syncthreads();
        if (t < 10) {
            float n2 = 0.f;
            #pragma unroll
            for (int mm = 0; mm < 16; mm++) { float v = sfull[t * 16 + mm]; n2 += v * v; }
            sscale[t] = (n2 / (1.f + n2)) / sqrtf(n2 + EPSF);
        }
        __syncthreads();
        if (t < 160) sv[t] = sfull[t] * sscale[t >> 4];
        __syncthreads();

        if (iter < 2) {
            for (int idx = t; idx < 11520; idx += 288) {
                int j = idx % 10;
                const float4* up4 = (const float4*)(ub + (size_t)idx * 16);
                const float4* vv4 = (const float4*)(sv + j * 16);
                float d = 0.f;
                #pragma unroll
                for (int q = 0; q < 4; q++) {
                    float4 a = up4[q], v4 = vv4[q];
                    d += a.x * v4.x + a.y * v4.y + a.z * v4.z + a.w * v4.w;
                }
                if (iter == 0) sb[idx] = d; else sb[idx] += d;
            }
        }
        __syncthreads();
    }
    if (t < 10) {
        float n2 = 0.f;
        #pragma unroll
        for (int mm = 0; mm < 16; mm++) { float v = sv[t * 16 + mm]; n2 += v * v; }
        out[b * 10 + t] = sqrtf(n2 + EPSF);
    }
    if (t < 16) {
        float s = 0.f;
        const float* yb = y + b * 10;
        #pragma unroll
        for (int tt = 0; tt < 10; tt++) s += sv[t * 10 + tt] * yb[tt];
        g_masked[b * 16 + t] = s;
    }
}

// ---------------- FC GEMM ----------------
__global__ void gemm_kernel(const float* __restrict__ Wt, const float* __restrict__ bias,
                            float* __restrict__ out, int N, int K, int which) {
    __shared__ float As[16][16];
    __shared__ float Bs[16][17];
    const float* A; float* C;
    if (which == 0)      { A = g_masked; C = g_fc1; }
    else if (which == 1) { A = g_fc1;    C = g_fc2; }
    else                 { A = g_fc2;    C = out + 2560; }
    int tx = threadIdx.x, ty = threadIdx.y;
    int n0 = blockIdx.x * 16, m0 = blockIdx.y * 16;
    float acc = 0.f;
    for (int k0 = 0; k0 < K; k0 += 16) {
        As[ty][tx] = A[(size_t)(m0 + ty) * K + k0 + tx];
        Bs[ty][tx] = Wt[(size_t)(n0 + ty) * K + k0 + tx];
        __syncthreads();
        #pragma unroll
        for (int kk = 0; kk < 16; kk++) acc += As[ty][kk] * Bs[tx][kk];
        __syncthreads();
    }
    acc += bias[n0 + tx];
    if (which == 2) acc = 1.f / (1.f + expf(-acc));
    C[(size_t)(m0 + ty) * N + n0 + tx] = acc;
}

// ---------------- launch ----------------
extern "C" void kernel_launch(void* const* d_in, const int* in_sizes, int n_in,
                              void* d_out, int out_size) {
    (void)in_sizes; (void)n_in; (void)out_size;
    const float* x   = (const float*)d_in[0];
    const float* y   = (const float*)d_in[1];
    const float* c1w = (const float*)d_in[2];
    const float* c1b = (const float*)d_in[3];
    const float* c2w = (const float*)d_in[4];
    const float* c2b = (const float*)d_in[5];
    const float* W   = (const float*)d_in[6];
    const float* br  = (const float*)d_in[7];
    const float* f1w = (const float*)d_in[8];
    const float* f1b = (const float*)d_in[9];
    const float* f2w = (const float*)d_in[10];
    const float* f2b = (const float*)d_in[11];
    const float* f3w = (const float*)d_in[12];
    const float* f3b = (const float*)d_in[13];
    float* out = (float*)d_out;

    prep_w_kernel<<<dim3(81, 256), 256>>>(c2w);
    conv1_kernel<<<dim3(8, 256), 256>>>(x, c1w, c1b);
    caps1_mma_kernel<<<dim3(2, 144), 128, SMEM_C1>>>(c2b);
    u_kernel<<<dim3(256, 8), 256>>>(W);
    routing_kernel<<<256, 288>>>(y, br, out);
    gemm_kernel<<<dim3(32, 16), dim3(16, 16)>>>(f1w, f1b, out, 512, 16, 0);
    gemm_kernel<<<dim3(64, 16), dim3(16, 16)>>>(f2w, f2b, out, 1024, 512, 1);
    gemm_kernel<<<dim3(49, 16), dim3(16, 16)>>>(f3w, f3b, out, 784, 1024, 2);
}

// round 10
// speedup vs baseline: 2.9475x; 1.1863x over previous
#include <cuda_runtime.h>
#include <cuda_fp16.h>
#include <cstdint>

#define EPSF 1e-9f
typedef unsigned long long u64;
typedef unsigned int u32;

// ---------------- persistent device scratch ----------------
__device__ __half g_h1h[256*400*256];          // conv1 out NHWC fp16  52MB
__device__ __half g_wh[256*20736];             // caps1 W [co][tap*256+ci] fp16
__device__ float g_h2[256*256*36];             // caps1 out (relu'd)  [b][co][36]
__device__ float g_u[256u*1152*10*16];         // prediction vectors  189MB
__device__ float g_blog[256*11520];            // routing logits
__device__ float g_masked[256*16];
__device__ float g_fc1[256*512];
__device__ float g_fc2[256*1024];

// ---------------- helpers ----------------
__device__ __forceinline__ void fma2(u64& acc, u64 a, u64 b) {
    asm("fma.rn.f32x2 %0, %1, %2, %0;" : "+l"(acc) : "l"(a), "l"(b));
}
__device__ __forceinline__ u64 pack2(float lo, float hi) {
    u64 r; unsigned il = __float_as_uint(lo), ih = __float_as_uint(hi);
    asm("mov.b64 %0, {%1, %2};" : "=l"(r) : "r"(il), "r"(ih));
    return r;
}
__device__ __forceinline__ u64 pack_dup(float v) {
    u64 r; unsigned iv = __float_as_uint(v);
    asm("mov.b64 %0, {%1, %1};" : "=l"(r) : "r"(iv));
    return r;
}
__device__ __forceinline__ void unpack2(u64 v, float& lo, float& hi) {
    asm("mov.b64 {%0, %1}, %2;" : "=f"(lo), "=f"(hi) : "l"(v));
}
__device__ __forceinline__ u32 smem_u32(const void* p) {
    u32 a;
    asm("{ .reg .u64 t; cvta.to.shared.u64 t, %1; cvt.u32.u64 %0, t; }" : "=r"(a) : "l"(p));
    return a;
}
__device__ __forceinline__ void cp16(u32 dst, const void* src) {
    asm volatile("cp.async.cg.shared.global [%0], [%1], 16;" :: "r"(dst), "l"(src) : "memory");
}
__device__ __forceinline__ void cp_commit() { asm volatile("cp.async.commit_group;" ::: "memory"); }
#define CP_WAIT(n) asm volatile("cp.async.wait_group %0;" :: "n"(n) : "memory")

// fp16 warp MMA m16n8k16, fp32 accum
#define MMAF16(c, a, b0, b1) \
    asm volatile("mma.sync.aligned.m16n8k16.row.col.f32.f16.f16.f32 " \
        "{%0,%1,%2,%3}, {%4,%5,%6,%7}, {%8,%9}, {%0,%1,%2,%3};" \
        : "+f"((c)[0]), "+f"((c)[1]), "+f"((c)[2]), "+f"((c)[3]) \
        : "r"((a)[0]), "r"((a)[1]), "r"((a)[2]), "r"((a)[3]), "r"(b0), "r"(b1))

// ---------------- weight prep: w[co][ci][9][9] fp32 -> g_wh[co][tap*256+ci] fp16 ----------------
__global__ void prep_w_kernel(const float* __restrict__ w) {
    int k  = blockIdx.x * 256 + threadIdx.x;   // 0..20735 (grid.x = 81)
    int co = blockIdx.y;
    int tap = k >> 8, ci = k & 255;
    g_wh[(size_t)co * 20736 + k] = __float2half(w[(size_t)co * 20736 + ci * 81 + tap]);
}

// ---------------- conv1: (B,1,28,28) -> relu -> NHWC fp16 (B,20,20,256) ----------------
__global__ __launch_bounds__(256)
void conv1_kernel(const float* __restrict__ x, const float* __restrict__ w,
                  const float* __restrict__ bias) {
    __shared__ float img[784];
    __shared__ float ws[2592];                 // layout [tap][32 co]
    int b = blockIdx.y, co0 = blockIdx.x * 32;
    int tid = threadIdx.x;
    for (int i = tid; i < 784; i += 256) img[i] = x[b * 784 + i];
    for (int i = tid; i < 2592; i += 256) {
        int t = i >> 5, c = i & 31;
        ws[i] = w[(co0 + c) * 81 + t];
    }
    u64 b2[16];
    #pragma unroll
    for (int c = 0; c < 16; c++) b2[c] = pack2(bias[co0 + 2*c], bias[co0 + 2*c + 1]);
    __syncthreads();

    for (int p = tid; p < 400; p += 256) {
        int oy = p / 20, ox = p % 20;
        u64 acc[16];
        #pragma unroll
        for (int c = 0; c < 16; c++) acc[c] = b2[c];
        #pragma unroll 1
        for (int dy = 0; dy < 9; dy++) {
            const float* row = img + (oy + dy) * 28 + ox;
            u64 rr[9];
            #pragma unroll
            for (int dx = 0; dx < 9; dx++) rr[dx] = pack_dup(row[dx]);
            #pragma unroll
            for (int dx = 0; dx < 9; dx++) {
                const u64* wp = (const u64*)(ws + (dy * 9 + dx) * 32);
                #pragma unroll
                for (int c = 0; c < 16; c++) fma2(acc[c], wp[c], rr[dx]);
            }
        }
        size_t base = ((size_t)b * 400 + p) * 256 + co0;
        #pragma unroll
        for (int c = 0; c < 16; c++) {
            float lo, hi; unpack2(acc[c], lo, hi);
            *reinterpret_cast<__half2*>(&g_h1h[base + 2*c]) =
                __halves2half2(__float2half(fmaxf(lo, 0.f)), __float2half(fmaxf(hi, 0.f)));
        }
    }
}

// ---------------- caps1 via mma.sync fp16: C[9216,256] = A[9216,20736] @ W^T ----------------
// 128 threads (4 warps 2x2), CTA tile M=64 x N=128, 2 CTAs/SM.
// K-step 16, 1296 steps, pure fp16 operands (1 MMA per tile), 4-stage cp.async.
// stage: A 3K | B 6K (48B pitch rows) = 9KB; 4 stages = 36KB.
static constexpr int CSTG = 9216;
static constexpr u32 SMEM_C1 = 4 * CSTG;   // 36864 < 48KB default

__global__ __launch_bounds__(128, 2)
void caps1_mma_kernel(const float* __restrict__ bias) {
    extern __shared__ char smem[];
    u32 sm = smem_u32(smem);
    int tid = threadIdx.x;
    int n0 = blockIdx.x * 128, m0 = blockIdx.y * 64;

    // loader: rw = tid>>1 (0..63), ch = tid&1 (16B chunk = 8 fp16)
    int rw = tid >> 1, ch = tid & 1;
    int pl = m0 + rw;
    int pb = pl / 36, prr = pl % 36, loy = prr / 6, lox = prr % 6;
    u32 aPix  = (u32)((pb * 20 + 2 * loy) * 20 + 2 * lox) * 256 + ch * 8;
    u32 bRow0 = (u32)(n0 + rw) * 20736 + ch * 8;
    u32 bRow1 = (u32)(n0 + rw + 64) * 20736 + ch * 8;
    u32 aOff  = (u32)(rw * 48 + ch * 16);
    u32 bOff0 = aOff;
    u32 bOff1 = (u32)((rw + 64) * 48 + ch * 16);

    auto load_stage = [&](int s, int step) {
        u32 base = sm + s * CSTG;
        int tap = step >> 4, ci0 = (step & 15) * 16;
        int dy = tap / 9, dx = tap - dy * 9;
        u32 asrc = aPix + (u32)(dy * 20 + dx) * 256 + ci0;
        u32 bs = (u32)tap * 256 + ci0;
        cp16(base + aOff,         g_h1h + asrc);
        cp16(base + 3072 + bOff0, g_wh + bRow0 + bs);
        cp16(base + 3072 + bOff1, g_wh + bRow1 + bs);
        cp_commit();
    };

    int wid = tid >> 5, lane = tid & 31;
    int wm = wid & 1, wn = wid >> 1;               // warp tile: M 32, N 64
    int g = lane >> 2, tc = lane & 3;

    float c[2][8][4];
    #pragma unroll
    for (int i = 0; i < 2; i++)
        #pragma unroll
        for (int j = 0; j < 8; j++)
            #pragma unroll
            for (int q = 0; q < 4; q++) c[i][j][q] = 0.f;

    load_stage(0, 0);
    load_stage(1, 1);
    load_stage(2, 2);

    #pragma unroll 1
    for (int step = 0; step < 1296; step++) {
        int cur = step & 3;
        CP_WAIT(2);                            // stage cur complete
        __syncthreads();                       // all warps done with stage being overwritten
        if (step + 3 < 1296) load_stage((step + 3) & 3, step + 3);

        const u32* Ah = (const u32*)(smem + cur * CSTG);
        const u32* Bh = Ah + 768;      // +3072B
        u32 ah[2][4];
        #pragma unroll
        for (int tm = 0; tm < 2; tm++) {
            int r = wm * 32 + tm * 16 + g;
            ah[tm][0] = Ah[r * 12 + tc];       ah[tm][1] = Ah[(r + 8) * 12 + tc];
            ah[tm][2] = Ah[r * 12 + tc + 4];   ah[tm][3] = Ah[(r + 8) * 12 + tc + 4];
        }
        #pragma unroll
        for (int tn = 0; tn < 8; tn++) {
            int n = wn * 64 + tn * 8 + g;
            u32 bh0 = Bh[n * 12 + tc], bh1 = Bh[n * 12 + tc + 4];
            #pragma unroll
            for (int tm = 0; tm < 2; tm++)
                MMAF16(c[tm][tn], ah[tm], bh0, bh1);
        }
    }
    __syncthreads();

    // epilogue: bias + relu -> g_h2[b][co][36]
    #pragma unroll
    for (int tm = 0; tm < 2; tm++) {
        int r0 = m0 + wm * 32 + tm * 16 + g;
        int b0i = r0 / 36, rr0 = r0 % 36;
        int r1 = r0 + 8;
        int b1i = r1 / 36, rr1 = r1 % 36;
        float* d0 = g_h2 + (size_t)b0i * 9216 + rr0;
        float* d1 = g_h2 + (size_t)b1i * 9216 + rr1;
        #pragma unroll
        for (int tn = 0; tn < 8; tn++) {
            int cc = n0 + wn * 64 + tn * 8 + tc * 2;
            float bv0 = bias[cc], bv1 = bias[cc + 1];
            d0[(size_t)cc * 36]       = fmaxf(c[tm][tn][0] + bv0, 0.f);
            d0[(size_t)(cc + 1) * 36] = fmaxf(c[tm][tn][1] + bv1, 0.f);
            d1[(size_t)cc * 36]       = fmaxf(c[tm][tn][2] + bv0, 0.f);
            d1[(size_t)(cc + 1) * 36] = fmaxf(c[tm][tn][3] + bv1, 0.f);
        }
    }
}

// ---------------- u = Wj @ x_tile, warp-per-row ----------------
__global__ __launch_bounds__(256)
void u_kernel(const float* __restrict__ W) {
    __shared__ __align__(16) float sx[9216];
    int b = blockIdx.x, chunk = blockIdx.y;
    int tid = threadIdx.x, wid = tid >> 5, lane = tid & 31;
    const float* h2b = g_h2 + (size_t)b * 9216;
    for (int i = tid; i < 9216; i += 256) sx[i] = h2b[i];
    __syncthreads();

    int half = lane & 1, mm = lane >> 1;
    float* ub = g_u + (size_t)b * 184320;

    #pragma unroll 4
    for (int k = 0; k < 180; k++) {
        int r = chunk * 1440 + wid + 8 * k;
        float4 w4 = reinterpret_cast<const float4*>(W)[(size_t)r * 32 + lane];
        int qb = r * 8 + half * 4;
        int base = (qb / 360) * 36 + (qb % 36);
        float4 x4 = *reinterpret_cast<const float4*>(&sx[base]);
        float p = w4.x * x4.x + w4.y * x4.y + w4.z * x4.z + w4.w * x4.w;
        float s = p + __shfl_xor_sync(0xFFFFFFFFu, p, 1);
        if (half == 0) ub[(size_t)r * 16 + mm] = s;
    }
}

// ---------------- dynamic routing (3 iters), one block per batch ----------------
__global__ __launch_bounds__(288)
void routing_kernel(const float* __restrict__ y, const float* __restrict__ bias_r,
                    float* __restrict__ out) {
    __shared__ float spart[18 * 160];
    __shared__ float sfull[160];
    __shared__ __align__(16) float sv[160];
    __shared__ float sscale[16];
    int b = blockIdx.x, t = threadIdx.x;
    const float* ub = g_u + (size_t)b * 184320;
    float* sb = g_blog + (size_t)b * 11520;
    int g = t >> 4, m = t & 15;

    for (int iter = 0; iter < 3; ++iter) {
        float acc[10];
        #pragma unroll
        for (int j = 0; j < 10; j++) acc[j] = 0.f;
        int i0 = g * 64;
        for (int i = i0; i < i0 + 64; i++) {
            float c[10];
            if (iter == 0) {
                #pragma unroll
                for (int j = 0; j < 10; j++) c[j] = 0.1f;
            } else {
                float mx = -1e30f;
                #pragma unroll
                for (int j = 0; j < 10; j++) { c[j] = sb[i * 10 + j]; mx = fmaxf(mx, c[j]); }
                float s = 0.f;
                #pragma unroll
                for (int j = 0; j < 10; j++) { c[j] = __expf(c[j] - mx); s += c[j]; }
                float inv = 1.f / s;
                #pragma unroll
                for (int j = 0; j < 10; j++) c[j] *= inv;
            }
            const float* up = ub + (size_t)i * 160 + m;
            #pragma unroll
            for (int j = 0; j < 10; j++) acc[j] += c[j] * up[j * 16];
        }
        #pragma unroll
        for (int j = 0; j < 10; j++) spart[g * 160 + j * 16 + m] = acc[j];
        __syncthreads();

        if (t < 160) {
            float s = bias_r[t];
            #pragma unroll
            for (int g2 = 0; g2 < 18; g2++) s += spart[g2 * 160 + t];
            sfull[t] = s;
        }
        __syncthreads();
        if (t < 10) {
            float n2 = 0.f;
            #pragma unroll
            for (int mm = 0; mm < 16; mm++) { float v = sfull[t * 16 + mm]; n2 += v * v; }
            sscale[t] = (n2 / (1.f + n2)) / sqrtf(n2 + EPSF);
        }
        __syncthreads();
        if (t < 160) sv[t] = sfull[t] * sscale[t >> 4];
        __syncthreads();

        if (iter < 2) {
            for (int idx = t; idx < 11520; idx += 288) {
                int j = idx % 10;
                const float4* up4 = (const float4*)(ub + (size_t)idx * 16);
                const float4* vv4 = (const float4*)(sv + j * 16);
                float d = 0.f;
                #pragma unroll
                for (int q = 0; q < 4; q++) {
                    float4 a = up4[q], v4 = vv4[q];
                    d += a.x * v4.x + a.y * v4.y + a.z * v4.z + a.w * v4.w;
                }
                if (iter == 0) sb[idx] = d; else sb[idx] += d;
            }
        }
        __syncthreads();
    }
    if (t < 10) {
        float n2 = 0.f;
        #pragma unroll
        for (int mm = 0; mm < 16; mm++) { float v = sv[t * 16 + mm]; n2 += v * v; }
        out[b * 10 + t] = sqrtf(n2 + EPSF);
    }
    if (t < 16) {
        float s = 0.f;
        const float* yb = y + b * 10;
        #pragma unroll
        for (int tt = 0; tt < 10; tt++) s += sv[t * 10 + tt] * yb[tt];
        g_masked[b * 16 + t] = s;
    }
}

// ---------------- FC GEMM ----------------
__global__ void gemm_kernel(const float* __restrict__ Wt, const float* __restrict__ bias,
                            float* __restrict__ out, int N, int K, int which) {
    __shared__ float As[16][16];
    __shared__ float Bs[16][17];
    const float* A; float* C;
    if (which == 0)      { A = g_masked; C = g_fc1; }
    else if (which == 1) { A = g_fc1;    C = g_fc2; }
    else                 { A = g_fc2;    C = out + 2560; }
    int tx = threadIdx.x, ty = threadIdx.y;
    int n0 = blockIdx.x * 16, m0 = blockIdx.y * 16;
    float acc = 0.f;
    for (int k0 = 0; k0 < K; k0 += 16) {
        As[ty][tx] = A[(size_t)(m0 + ty) * K + k0 + tx];
        Bs[ty][tx] = Wt[(size_t)(n0 + ty) * K + k0 + tx];
        __syncthreads();
        #pragma unroll
        for (int kk = 0; kk < 16; kk++) acc += As[ty][kk] * Bs[tx][kk];
        __syncthreads();
    }
    acc += bias[n0 + tx];
    if (which == 2) acc = 1.f / (1.f + expf(-acc));
    C[(size_t)(m0 + ty) * N + n0 + tx] = acc;
}

// ---------------- launch ----------------
extern "C" void kernel_launch(void* const* d_in, const int* in_sizes, int n_in,
                              void* d_out, int out_size) {
    (void)in_sizes; (void)n_in; (void)out_size;
    const float* x   = (const float*)d_in[0];
    const float* y   = (const float*)d_in[1];
    const float* c1w = (const float*)d_in[2];
    const float* c1b = (const float*)d_in[3];
    const float* c2w = (const float*)d_in[4];
    const float* c2b = (const float*)d_in[5];
    const float* W   = (const float*)d_in[6];
    const float* br  = (const float*)d_in[7];
    const float* f1w = (const float*)d_in[8];
    const float* f1b = (const float*)d_in[9];
    const float* f2w = (const float*)d_in[10];
    const float* f2b = (const float*)d_in[11];
    const float* f3w = (const float*)d_in[12];
    const float* f3b = (const float*)d_in[13];
    float* out = (float*)d_out;

    prep_w_kernel<<<dim3(81, 256), 256>>>(c2w);
    conv1_kernel<<<dim3(8, 256), 256>>>(x, c1w, c1b);
    caps1_mma_kernel<<<dim3(2, 144), 128, SMEM_C1>>>(c2b);
    u_kernel<<<dim3(256, 8), 256>>>(W);
    routing_kernel<<<256, 288>>>(y, br, out);
    gemm_kernel<<<dim3(32, 16), dim3(16, 16)>>>(f1w, f1b, out, 512, 16, 0);
    gemm_kernel<<<dim3(64, 16), dim3(16, 16)>>>(f2w, f2b, out, 1024, 512, 1);
    gemm_kernel<<<dim3(49, 16), dim3(16, 16)>>>(f3w, f3b, out, 784, 1024, 2);
}